// round 5
// baseline (speedup 1.0000x reference)
#include <cuda_runtime.h>
#include <cuda_fp16.h>
#include <cstdint>

// ============================================================================
// BilinearChebConv via mma.sync (fp16 3-way split GEMMs, fp32 accumulate)
// out[o] = sum_{i,j} theta[i,j,o] * (Tr_i @ X @ Tc_j) + bias[o]
// M = N = 1536, orders 4/4, OUT = 32.
// R5: warp K-split 64x64 tiles (halved ldmatrix traffic), 3-stage cp.async
// pipeline with load-before-compute, split-major mma ordering.
// ============================================================================

constexpr int NM   = 1536;
constexpr int N2   = NM * NM;
constexpr int OUTC = 32;

constexpr int BK    = 64;                 // k per stage (64 fp16 = 128B row)
constexpr int NKT   = NM / BK;            // 24
constexpr int PLANE = 128 * 128;          // bytes per operand plane per stage
constexpr int STAGE = 4 * PLANE;          // Ah|Al|Bh|Bl = 64 KB
constexpr unsigned SMEM_DYN = 3 * STAGE;  // 192 KB (3 stages; reduction aliases)

// ----------------------------------------------------------------------------
// Scratch (no cudaMalloc allowed -> __device__ globals)
__device__ float g_Tr32[3][N2];
__device__ float g_Tc32[3][N2];
__device__ float g_W32[4][N2];          // W_j = X @ Tc_j      (= Z_{0,j})
__device__ float g_Y32[4][N2];          // Y_i = Tr_i @ X      (= Z_{i,0})
__device__ float g_Z32[16][N2];         // Z_ij = Tr_i @ W_j,  i,j = 1..4
// fp16 hi/lo operand planes (all B operands stored as N x K)
__device__ __half g_Xh[N2],  g_Xl[N2];      // X   (A operand, row-major)
__device__ __half g_XTh[N2], g_XTl[N2];     // X^T (B operand for Y-stage)
__device__ __half g_Lrh[N2], g_Lrl[N2];
__device__ __half g_Lch[N2], g_Lcl[N2];
__device__ __half g_Trh[3][N2], g_Trl[3][N2];   // symmetric -> B directly
__device__ __half g_Tch[3][N2], g_Tcl[3][N2];
__device__ __half g_WTh[4][N2], g_WTl[4][N2];   // W_j^T (B for Z-stage)

// ----------------------------------------------------------------------------
// PTX helpers (all baseline sm_80+ instructions)
// ----------------------------------------------------------------------------
__device__ __forceinline__ uint32_t smem_u32(const void* p) {
    uint32_t a;
    asm("{ .reg .u64 t; cvta.to.shared.u64 t, %1; cvt.u32.u64 %0, t; }"
        : "=r"(a) : "l"(p));
    return a;
}
__device__ __forceinline__ void cpa16(uint32_t s, const void* g) {
    asm volatile("cp.async.cg.shared.global [%0], [%1], 16;\n" :: "r"(s), "l"(g));
}
__device__ __forceinline__ void cp_commit() {
    asm volatile("cp.async.commit_group;\n" ::: "memory");
}
__device__ __forceinline__ void cp_wait1() {
    asm volatile("cp.async.wait_group 1;\n" ::: "memory");
}
__device__ __forceinline__ void ldsm4(uint32_t* r, uint32_t a) {
    asm volatile("ldmatrix.sync.aligned.m8n8.x4.shared.b16 {%0,%1,%2,%3}, [%4];"
                 : "=r"(r[0]), "=r"(r[1]), "=r"(r[2]), "=r"(r[3]) : "r"(a));
}
__device__ __forceinline__ void mma16816(float* c, const uint32_t* a,
                                         uint32_t b0, uint32_t b1) {
    asm volatile("mma.sync.aligned.m16n8k16.row.col.f32.f16.f16.f32 "
                 "{%0,%1,%2,%3}, {%4,%5,%6,%7}, {%8,%9}, {%0,%1,%2,%3};"
                 : "+f"(c[0]), "+f"(c[1]), "+f"(c[2]), "+f"(c[3])
                 : "r"(a[0]), "r"(a[1]), "r"(a[2]), "r"(a[3]), "r"(b0), "r"(b1));
}

extern __shared__ char dsm[];

// ----------------------------------------------------------------------------
// Core GEMM: C(128x128) += 3-split product over K=1536.
// 8 warps: 4 spatial 64x64 tiles x 2 K-groups. acc[4][8][4] per thread.
// After mainloop, K-group pairs reduce through smem; each warp ends up
// owning cols [wn + ks*32, wn + ks*32 + 32) of its 64x64 tile.
// ----------------------------------------------------------------------------
__device__ __forceinline__ void gemm_main(
    const __half* __restrict__ Ah, const __half* __restrict__ Al,
    const __half* __restrict__ Bh, const __half* __restrict__ Bl,
    float (&acc)[4][8][4])
{
    const uint32_t sbase = smem_u32(dsm);
    const int tid = threadIdx.x, lane = tid & 31, wid = tid >> 5;
    const int p = wid & 3, ks = wid >> 2;
    const int wm = (p & 1) * 64, wn = (p >> 1) * 64;
    const int l15 = lane & 15, lhi = lane >> 4;
    const int bm = blockIdx.y * 128, bn = blockIdx.x * 128;
    const int lc = tid & 7, lr = tid >> 3;     // loader: chunk 0..7, row 0..31

    auto load_stage = [&](int st, int kc) {
        const uint32_t sb = sbase + st * STAGE;
#pragma unroll
        for (int rr = 0; rr < 128; rr += 32) {
            const int r = lr + rr;
            const uint32_t off = (uint32_t)(r * 128) + (uint32_t)((lc ^ (r & 7)) << 4);
            const size_t ga = (size_t)(bm + r) * NM + kc + lc * 8;
            const size_t gb = (size_t)(bn + r) * NM + kc + lc * 8;
            cpa16(sb + 0 * PLANE + off, Ah + ga);
            cpa16(sb + 1 * PLANE + off, Al + ga);
            cpa16(sb + 2 * PLANE + off, Bh + gb);
            cpa16(sb + 3 * PLANE + off, Bl + gb);
        }
    };

    load_stage(0, 0);  cp_commit();
    load_stage(1, BK); cp_commit();

    for (int kt = 0; kt < NKT; ++kt) {
        cp_wait1();                 // stage kt resident
        __syncthreads();            // all warps past compute kt-1
        if (kt + 2 < NKT) load_stage((kt + 2) % 3, (kt + 2) * BK);
        cp_commit();
        const uint32_t sb = sbase + (kt % 3) * STAGE;
#pragma unroll
        for (int kh2 = 0; kh2 < 2; ++kh2) {
            const int kh = ks + 2 * kh2;           // this warp's k16 slice
            const int chunkL = (kh << 1) | lhi;
            uint32_t ahf[4][4], alf[4][4];
#pragma unroll
            for (int mt = 0; mt < 4; ++mt) {
                const int r = wm + mt * 16 + l15;
                const uint32_t off = (uint32_t)(r * 128) +
                                     (uint32_t)((chunkL ^ (r & 7)) << 4);
                ldsm4(ahf[mt], sb + 0 * PLANE + off);
                ldsm4(alf[mt], sb + 1 * PLANE + off);
            }
#pragma unroll
            for (int g = 0; g < 4; ++g) {
                uint32_t bh4[4], bl4[4];
                const int r = wn + g * 16 + l15;
                const uint32_t off = (uint32_t)(r * 128) +
                                     (uint32_t)((chunkL ^ (r & 7)) << 4);
                ldsm4(bh4, sb + 2 * PLANE + off);
                ldsm4(bl4, sb + 3 * PLANE + off);
                // split-major: same-acc reuse distance = 8 mmas
#pragma unroll
                for (int mt = 0; mt < 4; ++mt)
#pragma unroll
                    for (int j = 0; j < 2; ++j)
                        mma16816(acc[mt][g * 2 + j], ahf[mt], bh4[j], bh4[j + 2]);
#pragma unroll
                for (int mt = 0; mt < 4; ++mt)
#pragma unroll
                    for (int j = 0; j < 2; ++j)
                        mma16816(acc[mt][g * 2 + j], alf[mt], bh4[j], bh4[j + 2]);
#pragma unroll
                for (int mt = 0; mt < 4; ++mt)
#pragma unroll
                    for (int j = 0; j < 2; ++j)
                        mma16816(acc[mt][g * 2 + j], ahf[mt], bl4[j], bl4[j + 2]);
            }
        }
    }

    // ---- K-group pair reduction through smem (stage buffers are dead) ----
    float* sred = (float*)dsm;      // [wid][128][32] floats, 128 KB used
    __syncthreads();
    const int oh = (ks ^ 1) * 4;    // half my partner epilogues (I store it)
#pragma unroll
    for (int mt = 0; mt < 4; ++mt)
#pragma unroll
        for (int gg = 0; gg < 4; ++gg)
#pragma unroll
            for (int e = 0; e < 4; ++e) {
                const int i = mt * 32 + (oh + gg) * 4 + e;
                sred[(wid * 128 + i) * 32 + lane] = acc[mt][oh + gg][e];
            }
    __syncthreads();
    const int mh = ks * 4;          // half I epilogue (partner stored it)
    const int pw = wid ^ 4;
#pragma unroll
    for (int mt = 0; mt < 4; ++mt)
#pragma unroll
        for (int gg = 0; gg < 4; ++gg)
#pragma unroll
            for (int e = 0; e < 4; ++e) {
                const int i = mt * 32 + (mh + gg) * 4 + e;
                acc[mt][mh + gg][e] += sred[(pw * 128 + i) * 32 + lane];
            }
}

// plain fp32 epilogue: each warp writes rows [wm,wm+64), cols [wn+ks*32,+32)
__device__ __forceinline__ void epi_plain(float (&acc)[4][8][4], float* __restrict__ C)
{
    const int tid = threadIdx.x, lane = tid & 31, wid = tid >> 5;
    const int p = wid & 3, ks = wid >> 2;
    const int wm = (p & 1) * 64, wn = (p >> 1) * 64;
    const int bm = blockIdx.y * 128, bn = blockIdx.x * 128;
    const int l4 = lane >> 2, l2 = (lane & 3) * 2;
#pragma unroll
    for (int mt = 0; mt < 4; ++mt)
#pragma unroll
        for (int h = 0; h < 2; ++h) {
            const int row = bm + wm + mt * 16 + l4 + h * 8;
#pragma unroll
            for (int gg = 0; gg < 4; ++gg) {
                const int g = ks * 4 + gg;
                const int col = bn + wn + g * 8 + l2;
                *(float2*)(C + (size_t)row * NM + col) =
                    make_float2(acc[mt][g][2 * h], acc[mt][g][2 * h + 1]);
            }
        }
}

// ----------------------------------------------------------------------------
// Kernels
// ----------------------------------------------------------------------------

// Chebyshev step: T_step = 2 * L @ B - D. Writes fp32 + fp16 hi/lo (symmetric,
// so the row-major result doubles as the N x K B-operand).
__global__ void __launch_bounds__(256)
k_gemm_cheb(const float* __restrict__ L32, int side, int step)
{
    const __half* Ah = side ? g_Lch : g_Lrh;
    const __half* Al = side ? g_Lcl : g_Lrl;
    const __half* Bh = (step == 0) ? Ah : (side ? g_Tch[step - 1] : g_Trh[step - 1]);
    const __half* Bl = (step == 0) ? Al : (side ? g_Tcl[step - 1] : g_Trl[step - 1]);
    const float* D = (step == 0) ? nullptr
                   : (step == 1) ? L32
                   : (side ? g_Tc32[0] : g_Tr32[0]);
    float* C = side ? g_Tc32[step] : g_Tr32[step];
    __half* Ho = side ? g_Tch[step] : g_Trh[step];
    __half* Lo = side ? g_Tcl[step] : g_Trl[step];

    float acc[4][8][4] = {};
    gemm_main(Ah, Al, Bh, Bl, acc);

    const int tid = threadIdx.x, lane = tid & 31, wid = tid >> 5;
    const int p = wid & 3, ks = wid >> 2;
    const int wm = (p & 1) * 64, wn = (p >> 1) * 64;
    const int bm = blockIdx.y * 128, bn = blockIdx.x * 128;
    const int l4 = lane >> 2, l2 = (lane & 3) * 2;
#pragma unroll
    for (int mt = 0; mt < 4; ++mt)
#pragma unroll
        for (int h = 0; h < 2; ++h) {
            const int row = bm + wm + mt * 16 + l4 + h * 8;
#pragma unroll
            for (int gg = 0; gg < 4; ++gg) {
                const int g = ks * 4 + gg;
                const int col = bn + wn + g * 8 + l2;
                const size_t off = (size_t)row * NM + col;
                float2 d;
                if (D) d = *(const float2*)(D + off);
                else   d = make_float2(row == col ? 1.f : 0.f,
                                       row == col + 1 ? 1.f : 0.f);
                const float vx = 2.f * acc[mt][g][2 * h]     - d.x;
                const float vy = 2.f * acc[mt][g][2 * h + 1] - d.y;
                *(float2*)(C + off) = make_float2(vx, vy);
                const __half hx = __float2half_rn(vx);
                const __half hy = __float2half_rn(vy);
                __half2 q;
                q.x = hx; q.y = hy;
                *(__half2*)(Ho + off) = q;
                q.x = __float2half_rn(vx - __half2float(hx));
                q.y = __float2half_rn(vy - __half2float(hy));
                *(__half2*)(Lo + off) = q;
            }
        }
}

// W_j = X @ Tc_j (j-1 = blockIdx.z); B symmetric.
__global__ void __launch_bounds__(256)
k_gemm_w()
{
    const int z = blockIdx.z;
    const __half* Bh = (z == 0) ? g_Lch : g_Tch[z - 1];
    const __half* Bl = (z == 0) ? g_Lcl : g_Tcl[z - 1];
    float acc[4][8][4] = {};
    gemm_main(g_Xh, g_Xl, Bh, Bl, acc);
    epi_plain(acc, g_W32[z]);
}

// Y_i = Tr_i @ X (i-1 = blockIdx.z); B = X^T planes.
__global__ void __launch_bounds__(256)
k_gemm_y()
{
    const int z = blockIdx.z;
    const __half* Ah = (z == 0) ? g_Lrh : g_Trh[z - 1];
    const __half* Al = (z == 0) ? g_Lrl : g_Trl[z - 1];
    float acc[4][8][4] = {};
    gemm_main(Ah, Al, g_XTh, g_XTl, acc);
    epi_plain(acc, g_Y32[z]);
}

// Z_ij = Tr_i @ W_j; z = (i-1)*4 + (j-1); B = W_j^T planes.
__global__ void __launch_bounds__(256)
k_gemm_z()
{
    const int z = blockIdx.z;
    const int i = z >> 2, j = z & 3;
    const __half* Ah = (i == 0) ? g_Lrh : g_Trh[i - 1];
    const __half* Al = (i == 0) ? g_Lrl : g_Trl[i - 1];
    float acc[4][8][4] = {};
    gemm_main(Ah, Al, g_WTh[j], g_WTl[j], acc);
    epi_plain(acc, g_Z32[z]);
}

// ----------------------------------------------------------------------------
// fp32 -> fp16 hi/lo conversion of inputs (z: 0=X, 1=Lr, 2=Lc)
__global__ void __launch_bounds__(256)
k_cvt(const float* __restrict__ x, const float* __restrict__ Lr,
      const float* __restrict__ Lc)
{
    const int zz = blockIdx.z;
    const float* s = (zz == 0) ? x : (zz == 1) ? Lr : Lc;
    __half* H = (zz == 0) ? g_Xh : (zz == 1) ? g_Lrh : g_Lch;
    __half* L = (zz == 0) ? g_Xl : (zz == 1) ? g_Lrl : g_Lcl;
    const int i = (blockIdx.x * 256 + threadIdx.x) * 4;
    float4 v = *(const float4*)(s + i);
    __half h0 = __float2half_rn(v.x), h1 = __float2half_rn(v.y);
    __half h2 = __float2half_rn(v.z), h3 = __float2half_rn(v.w);
    __half2 p;
    p.x = h0; p.y = h1; *(__half2*)(H + i)     = p;
    p.x = h2; p.y = h3; *(__half2*)(H + i + 2) = p;
    p.x = __float2half_rn(v.x - __half2float(h0));
    p.y = __float2half_rn(v.y - __half2float(h1));
    *(__half2*)(L + i) = p;
    p.x = __float2half_rn(v.z - __half2float(h2));
    p.y = __float2half_rn(v.w - __half2float(h3));
    *(__half2*)(L + i + 2) = p;
}

// X^T hi/lo
__global__ void __launch_bounds__(256)
k_cvtT(const float* __restrict__ X)
{
    __shared__ float t[32][33];
    const int tx = threadIdx.x, ty = threadIdx.y;
    const int n0 = blockIdx.x * 32, m0 = blockIdx.y * 32;
#pragma unroll
    for (int i = 0; i < 4; ++i)
        t[ty + 8 * i][tx] = X[(size_t)(m0 + ty + 8 * i) * NM + n0 + tx];
    __syncthreads();
#pragma unroll
    for (int i = 0; i < 4; ++i) {
        const int nl = ty + 8 * i;
        const float v = t[tx][nl];                    // X[m0+tx][n0+nl]
        const size_t off = (size_t)(n0 + nl) * NM + m0 + tx;
        __half h = __float2half_rn(v);
        g_XTh[off] = h;
        g_XTl[off] = __float2half_rn(v - __half2float(h));
    }
}

// W^T hi/lo (z = j-1)
__global__ void __launch_bounds__(256)
k_trW()
{
    const int z = blockIdx.z;
    const float* S = g_W32[z];
    __half* TH = g_WTh[z];
    __half* TL = g_WTl[z];
    __shared__ float t[32][33];
    const int tx = threadIdx.x, ty = threadIdx.y;
    const int n0 = blockIdx.x * 32, m0 = blockIdx.y * 32;
#pragma unroll
    for (int i = 0; i < 4; ++i)
        t[ty + 8 * i][tx] = S[(size_t)(m0 + ty + 8 * i) * NM + n0 + tx];
    __syncthreads();
#pragma unroll
    for (int i = 0; i < 4; ++i) {
        const int nl = ty + 8 * i;
        const float v = t[tx][nl];
        const size_t off = (size_t)(n0 + nl) * NM + m0 + tx;
        __half h = __float2half_rn(v);
        TH[off] = h;
        TL[off] = __float2half_rn(v - __half2float(h));
    }
}

// ----------------------------------------------------------------------------
// Final mix: out[o,m,n] = bias[o] + sum_t theta[t,o] * plane_t[m,n]
__global__ void __launch_bounds__(256)
k_mix(const float* __restrict__ x, const float* __restrict__ theta,
      const float* __restrict__ bias, float* __restrict__ out)
{
    __shared__ float sh_th[25 * OUTC];
    __shared__ float sh_b[OUTC];
    const int tid = threadIdx.x;
    for (int t = tid; t < 25 * OUTC; t += 256) sh_th[t] = theta[t];
    if (tid < OUTC) sh_b[tid] = bias[tid];
    __syncthreads();

    const int off = (blockIdx.x * 256 + tid) * 2;

    float2 v[25];
    v[0] = *(const float2*)(x + off);
#pragma unroll
    for (int j = 1; j <= 4; ++j) v[j] = *(const float2*)(g_W32[j - 1] + off);
#pragma unroll
    for (int i = 1; i <= 4; ++i) v[i * 5] = *(const float2*)(g_Y32[i - 1] + off);
#pragma unroll
    for (int i = 1; i <= 4; ++i)
#pragma unroll
        for (int j = 1; j <= 4; ++j)
            v[i * 5 + j] = *(const float2*)(g_Z32[(i - 1) * 4 + (j - 1)] + off);

#pragma unroll
    for (int o = 0; o < OUTC; ++o) {
        float sx = sh_b[o], sy = sh_b[o];
#pragma unroll
        for (int t = 0; t < 25; ++t) {
            const float w = sh_th[t * OUTC + o];
            sx += w * v[t].x;
            sy += w * v[t].y;
        }
        *(float2*)(out + (size_t)o * N2 + off) = make_float2(sx, sy);
    }
}

// ----------------------------------------------------------------------------
extern "C" void kernel_launch(void* const* d_in, const int* in_sizes, int n_in,
                              void* d_out, int out_size)
{
    const float* x     = (const float*)d_in[0];
    const float* Lr    = (const float*)d_in[1];
    const float* Lc    = (const float*)d_in[2];
    const float* theta = (const float*)d_in[3];
    const float* bias  = (const float*)d_in[4];
    float* out = (float*)d_out;

    cudaFuncSetAttribute(k_gemm_cheb, cudaFuncAttributeMaxDynamicSharedMemorySize, SMEM_DYN);
    cudaFuncSetAttribute(k_gemm_w,    cudaFuncAttributeMaxDynamicSharedMemorySize, SMEM_DYN);
    cudaFuncSetAttribute(k_gemm_y,    cudaFuncAttributeMaxDynamicSharedMemorySize, SMEM_DYN);
    cudaFuncSetAttribute(k_gemm_z,    cudaFuncAttributeMaxDynamicSharedMemorySize, SMEM_DYN);

    const dim3 blk(256);
    const dim3 g2(NM / 128, NM / 128, 1);        // (12,12)
    const dim3 blkT(32, 8);
    const dim3 gT(NM / 32, NM / 32, 1);

    // input conversions
    k_cvt<<<dim3(N2 / 1024, 1, 3), blk>>>(x, Lr, Lc);
    k_cvtT<<<gT, blkT>>>(x);

    // Chebyshev bases (sequential per side)
    for (int step = 0; step < 3; ++step)
        k_gemm_cheb<<<g2, blk, SMEM_DYN>>>(Lr, 0, step);
    for (int step = 0; step < 3; ++step)
        k_gemm_cheb<<<g2, blk, SMEM_DYN>>>(Lc, 1, step);

    // W_j = X @ Tc_j
    k_gemm_w<<<dim3(12, 12, 4), blk, SMEM_DYN>>>();
    // W^T hi/lo for the Z-stage B operands
    k_trW<<<dim3(NM / 32, NM / 32, 4), blkT>>>();
    // Y_i = Tr_i @ X
    k_gemm_y<<<dim3(12, 12, 4), blk, SMEM_DYN>>>();
    // Z_ij = Tr_i @ W_j
    k_gemm_z<<<dim3(12, 12, 16), blk, SMEM_DYN>>>();

    // final 25-term mix
    k_mix<<<N2 / 512, blk>>>(x, theta, bias, out);
}

// round 6
// speedup vs baseline: 2.1807x; 2.1807x over previous
#include <cuda_runtime.h>
#include <cuda_fp16.h>
#include <cstdint>

// ============================================================================
// BilinearChebConv via mma.sync (fp16 3-way split GEMMs, fp32 accumulate)
// out[o] = sum_{i,j} theta[i,j,o] * (Tr_i @ X @ Tc_j) + bias[o]
// M = N = 1536, orders 4/4, OUT = 32.
// R6 = R4 tile shape (64x32 warp tiles, 182 regs) + split-major MMA ordering
// (reuse distance 16 instead of 1) + 3-stage cp.async with load-first.
// ============================================================================

constexpr int NM   = 1536;
constexpr int N2   = NM * NM;
constexpr int OUTC = 32;

constexpr int BK    = 64;                 // k per stage (64 fp16 = 128B row)
constexpr int NKT   = NM / BK;            // 24
constexpr int PLANE = 128 * 128;          // bytes per operand plane per stage
constexpr int STAGE = 4 * PLANE;          // Ah|Al|Bh|Bl = 64 KB
constexpr unsigned SMEM_DYN = 3 * STAGE;  // 192 KB

// ----------------------------------------------------------------------------
// Scratch (no cudaMalloc allowed -> __device__ globals)
__device__ float g_Tr32[3][N2];
__device__ float g_Tc32[3][N2];
__device__ float g_W32[4][N2];          // W_j = X @ Tc_j      (= Z_{0,j})
__device__ float g_Y32[4][N2];          // Y_i = Tr_i @ X      (= Z_{i,0})
__device__ float g_Z32[16][N2];         // Z_ij = Tr_i @ W_j,  i,j = 1..4
// fp16 hi/lo operand planes (all B operands stored as N x K)
__device__ __half g_Xh[N2],  g_Xl[N2];      // X   (A operand, row-major)
__device__ __half g_XTh[N2], g_XTl[N2];     // X^T (B operand for Y-stage)
__device__ __half g_Lrh[N2], g_Lrl[N2];
__device__ __half g_Lch[N2], g_Lcl[N2];
__device__ __half g_Trh[3][N2], g_Trl[3][N2];   // symmetric -> B directly
__device__ __half g_Tch[3][N2], g_Tcl[3][N2];
__device__ __half g_WTh[4][N2], g_WTl[4][N2];   // W_j^T (B for Z-stage)

// ----------------------------------------------------------------------------
// PTX helpers (all baseline sm_80+ instructions)
// ----------------------------------------------------------------------------
__device__ __forceinline__ uint32_t smem_u32(const void* p) {
    uint32_t a;
    asm("{ .reg .u64 t; cvta.to.shared.u64 t, %1; cvt.u32.u64 %0, t; }"
        : "=r"(a) : "l"(p));
    return a;
}
__device__ __forceinline__ void cpa16(uint32_t s, const void* g) {
    asm volatile("cp.async.cg.shared.global [%0], [%1], 16;\n" :: "r"(s), "l"(g));
}
__device__ __forceinline__ void cp_commit() {
    asm volatile("cp.async.commit_group;\n" ::: "memory");
}
__device__ __forceinline__ void cp_wait2() {
    asm volatile("cp.async.wait_group 2;\n" ::: "memory");
}
__device__ __forceinline__ void ldsm4(uint32_t* r, uint32_t a) {
    asm volatile("ldmatrix.sync.aligned.m8n8.x4.shared.b16 {%0,%1,%2,%3}, [%4];"
                 : "=r"(r[0]), "=r"(r[1]), "=r"(r[2]), "=r"(r[3]) : "r"(a));
}
__device__ __forceinline__ void mma16816(float* c, const uint32_t* a,
                                         uint32_t b0, uint32_t b1) {
    asm volatile("mma.sync.aligned.m16n8k16.row.col.f32.f16.f16.f32 "
                 "{%0,%1,%2,%3}, {%4,%5,%6,%7}, {%8,%9}, {%0,%1,%2,%3};"
                 : "+f"(c[0]), "+f"(c[1]), "+f"(c[2]), "+f"(c[3])
                 : "r"(a[0]), "r"(a[1]), "r"(a[2]), "r"(a[3]), "r"(b0), "r"(b1));
}

extern __shared__ char dsm[];

// ----------------------------------------------------------------------------
// Core GEMM: C(128x128) += 3-split product over K=1536.
// Block = 256 threads, 8 warps of 64x32. acc[4][4][4] per thread.
// Smem rows are 128B with SW128 xor swizzle -> conflict-free ldmatrix.
// ----------------------------------------------------------------------------
__device__ __forceinline__ void gemm_main(
    const __half* __restrict__ Ah, const __half* __restrict__ Al,
    const __half* __restrict__ Bh, const __half* __restrict__ Bl,
    float (&acc)[4][4][4])
{
    const uint32_t sbase = smem_u32(dsm);
    const int tid = threadIdx.x, lane = tid & 31, wid = tid >> 5;
    const int wm = (wid & 1) * 64, wn = (wid >> 1) * 32;
    const int l15 = lane & 15, lhi = lane >> 4;
    const int bm = blockIdx.y * 128, bn = blockIdx.x * 128;
    const int lc = tid & 7, lr = tid >> 3;     // loader: chunk 0..7, row 0..31

    auto load_stage = [&](int st, int kc) {
        const uint32_t sb = sbase + st * STAGE;
#pragma unroll
        for (int rr = 0; rr < 128; rr += 32) {
            const int r = lr + rr;
            const uint32_t off = (uint32_t)(r * 128) + (uint32_t)((lc ^ (r & 7)) << 4);
            const size_t ga = (size_t)(bm + r) * NM + kc + lc * 8;
            const size_t gb = (size_t)(bn + r) * NM + kc + lc * 8;
            cpa16(sb + 0 * PLANE + off, Ah + ga);
            cpa16(sb + 1 * PLANE + off, Al + ga);
            cpa16(sb + 2 * PLANE + off, Bh + gb);
            cpa16(sb + 3 * PLANE + off, Bl + gb);
        }
    };

    load_stage(0, 0);      cp_commit();
    load_stage(1, BK);     cp_commit();
    load_stage(2, 2 * BK); cp_commit();

    for (int kt = 0; kt < NKT; ++kt) {
        cp_wait2();                 // stage kt resident (2 younger groups open)
        __syncthreads();            // all warps done with buffer (kt+3)%3 == kt%3
        const uint32_t sb = sbase + (kt % 3) * STAGE;
#pragma unroll
        for (int kh = 0; kh < 4; ++kh) {               // four k16 slices per stage
            uint32_t ahf[4][4], alf[4][4], bhf[2][4], blf[2][4];
            const int chunkL = (kh << 1) | lhi;        // logical 16B chunk
#pragma unroll
            for (int mt = 0; mt < 4; ++mt) {
                const int r = wm + mt * 16 + l15;
                const uint32_t off = (uint32_t)(r * 128) +
                                     (uint32_t)((chunkL ^ (r & 7)) << 4);
                ldsm4(ahf[mt], sb + 0 * PLANE + off);
                ldsm4(alf[mt], sb + 1 * PLANE + off);
            }
#pragma unroll
            for (int g = 0; g < 2; ++g) {
                const int r = wn + g * 16 + l15;
                const uint32_t off = (uint32_t)(r * 128) +
                                     (uint32_t)((chunkL ^ (r & 7)) << 4);
                ldsm4(bhf[g], sb + 2 * PLANE + off);
                ldsm4(blf[g], sb + 3 * PLANE + off);
            }
            // split-major passes: same-accumulator reuse distance = 16 MMAs
#pragma unroll
            for (int mt = 0; mt < 4; ++mt)
#pragma unroll
                for (int nt = 0; nt < 4; ++nt) {
                    const int g = nt >> 1, j = nt & 1;
                    mma16816(acc[mt][nt], ahf[mt], bhf[g][j], bhf[g][j + 2]);
                }
#pragma unroll
            for (int mt = 0; mt < 4; ++mt)
#pragma unroll
                for (int nt = 0; nt < 4; ++nt) {
                    const int g = nt >> 1, j = nt & 1;
                    mma16816(acc[mt][nt], alf[mt], bhf[g][j], bhf[g][j + 2]);
                }
#pragma unroll
            for (int mt = 0; mt < 4; ++mt)
#pragma unroll
                for (int nt = 0; nt < 4; ++nt) {
                    const int g = nt >> 1, j = nt & 1;
                    mma16816(acc[mt][nt], ahf[mt], blf[g][j], blf[g][j + 2]);
                }
        }
        __syncthreads();            // compute done before reloading this buffer
        if (kt + 3 < NKT) load_stage(kt % 3, (kt + 3) * BK);
        cp_commit();                // constant group accounting
    }
}

// plain fp32 epilogue -------------------------------------------------------
__device__ __forceinline__ void epi_plain(float (&acc)[4][4][4], float* __restrict__ C)
{
    const int tid = threadIdx.x, lane = tid & 31, wid = tid >> 5;
    const int wm = (wid & 1) * 64, wn = (wid >> 1) * 32;
    const int bm = blockIdx.y * 128, bn = blockIdx.x * 128;
    const int l4 = lane >> 2, l2 = (lane & 3) * 2;
#pragma unroll
    for (int mt = 0; mt < 4; ++mt)
#pragma unroll
        for (int h = 0; h < 2; ++h) {
            const int row = bm + wm + mt * 16 + l4 + h * 8;
#pragma unroll
            for (int nt = 0; nt < 4; ++nt) {
                const int col = bn + wn + nt * 8 + l2;
                *(float2*)(C + (size_t)row * NM + col) =
                    make_float2(acc[mt][nt][2 * h], acc[mt][nt][2 * h + 1]);
            }
        }
}

// ----------------------------------------------------------------------------
// Kernels
// ----------------------------------------------------------------------------

// Chebyshev step: T_step = 2 * L @ B - D. Writes fp32 + fp16 hi/lo (symmetric,
// so the row-major result doubles as the N x K B-operand).
__global__ void __launch_bounds__(256)
k_gemm_cheb(const float* __restrict__ L32, int side, int step)
{
    const __half* Ah = side ? g_Lch : g_Lrh;
    const __half* Al = side ? g_Lcl : g_Lrl;
    const __half* Bh = (step == 0) ? Ah : (side ? g_Tch[step - 1] : g_Trh[step - 1]);
    const __half* Bl = (step == 0) ? Al : (side ? g_Tcl[step - 1] : g_Trl[step - 1]);
    const float* D = (step == 0) ? nullptr
                   : (step == 1) ? L32
                   : (side ? g_Tc32[0] : g_Tr32[0]);
    float* C = side ? g_Tc32[step] : g_Tr32[step];
    __half* Ho = side ? g_Tch[step] : g_Trh[step];
    __half* Lo = side ? g_Tcl[step] : g_Trl[step];

    float acc[4][4][4] = {};
    gemm_main(Ah, Al, Bh, Bl, acc);

    const int tid = threadIdx.x, lane = tid & 31, wid = tid >> 5;
    const int wm = (wid & 1) * 64, wn = (wid >> 1) * 32;
    const int bm = blockIdx.y * 128, bn = blockIdx.x * 128;
    const int l4 = lane >> 2, l2 = (lane & 3) * 2;
#pragma unroll
    for (int mt = 0; mt < 4; ++mt)
#pragma unroll
        for (int h = 0; h < 2; ++h) {
            const int row = bm + wm + mt * 16 + l4 + h * 8;
#pragma unroll
            for (int nt = 0; nt < 4; ++nt) {
                const int col = bn + wn + nt * 8 + l2;
                const size_t off = (size_t)row * NM + col;
                float2 d;
                if (D) d = *(const float2*)(D + off);
                else   d = make_float2(row == col ? 1.f : 0.f,
                                       row == col + 1 ? 1.f : 0.f);
                const float vx = 2.f * acc[mt][nt][2 * h]     - d.x;
                const float vy = 2.f * acc[mt][nt][2 * h + 1] - d.y;
                *(float2*)(C + off) = make_float2(vx, vy);
                const __half hx = __float2half_rn(vx);
                const __half hy = __float2half_rn(vy);
                __half2 q;
                q.x = hx; q.y = hy;
                *(__half2*)(Ho + off) = q;
                q.x = __float2half_rn(vx - __half2float(hx));
                q.y = __float2half_rn(vy - __half2float(hy));
                *(__half2*)(Lo + off) = q;
            }
        }
}

// W_j = X @ Tc_j (j-1 = blockIdx.z); B symmetric.
__global__ void __launch_bounds__(256)
k_gemm_w()
{
    const int z = blockIdx.z;
    const __half* Bh = (z == 0) ? g_Lch : g_Tch[z - 1];
    const __half* Bl = (z == 0) ? g_Lcl : g_Tcl[z - 1];
    float acc[4][4][4] = {};
    gemm_main(g_Xh, g_Xl, Bh, Bl, acc);
    epi_plain(acc, g_W32[z]);
}

// Y_i = Tr_i @ X (i-1 = blockIdx.z); B = X^T planes.
__global__ void __launch_bounds__(256)
k_gemm_y()
{
    const int z = blockIdx.z;
    const __half* Ah = (z == 0) ? g_Lrh : g_Trh[z - 1];
    const __half* Al = (z == 0) ? g_Lrl : g_Trl[z - 1];
    float acc[4][4][4] = {};
    gemm_main(Ah, Al, g_XTh, g_XTl, acc);
    epi_plain(acc, g_Y32[z]);
}

// Z_ij = Tr_i @ W_j; z = (i-1)*4 + (j-1); B = W_j^T planes.
__global__ void __launch_bounds__(256)
k_gemm_z()
{
    const int z = blockIdx.z;
    const int i = z >> 2, j = z & 3;
    const __half* Ah = (i == 0) ? g_Lrh : g_Trh[i - 1];
    const __half* Al = (i == 0) ? g_Lrl : g_Trl[i - 1];
    float acc[4][4][4] = {};
    gemm_main(Ah, Al, g_WTh[j], g_WTl[j], acc);
    epi_plain(acc, g_Z32[z]);
}

// ----------------------------------------------------------------------------
// fp32 -> fp16 hi/lo conversion of inputs (z: 0=X, 1=Lr, 2=Lc)
__global__ void __launch_bounds__(256)
k_cvt(const float* __restrict__ x, const float* __restrict__ Lr,
      const float* __restrict__ Lc)
{
    const int zz = blockIdx.z;
    const float* s = (zz == 0) ? x : (zz == 1) ? Lr : Lc;
    __half* H = (zz == 0) ? g_Xh : (zz == 1) ? g_Lrh : g_Lch;
    __half* L = (zz == 0) ? g_Xl : (zz == 1) ? g_Lrl : g_Lcl;
    const int i = (blockIdx.x * 256 + threadIdx.x) * 4;
    float4 v = *(const float4*)(s + i);
    __half h0 = __float2half_rn(v.x), h1 = __float2half_rn(v.y);
    __half h2 = __float2half_rn(v.z), h3 = __float2half_rn(v.w);
    __half2 p;
    p.x = h0; p.y = h1; *(__half2*)(H + i)     = p;
    p.x = h2; p.y = h3; *(__half2*)(H + i + 2) = p;
    p.x = __float2half_rn(v.x - __half2float(h0));
    p.y = __float2half_rn(v.y - __half2float(h1));
    *(__half2*)(L + i) = p;
    p.x = __float2half_rn(v.z - __half2float(h2));
    p.y = __float2half_rn(v.w - __half2float(h3));
    *(__half2*)(L + i + 2) = p;
}

// X^T hi/lo
__global__ void __launch_bounds__(256)
k_cvtT(const float* __restrict__ X)
{
    __shared__ float t[32][33];
    const int tx = threadIdx.x, ty = threadIdx.y;
    const int n0 = blockIdx.x * 32, m0 = blockIdx.y * 32;
#pragma unroll
    for (int i = 0; i < 4; ++i)
        t[ty + 8 * i][tx] = X[(size_t)(m0 + ty + 8 * i) * NM + n0 + tx];
    __syncthreads();
#pragma unroll
    for (int i = 0; i < 4; ++i) {
        const int nl = ty + 8 * i;
        const float v = t[tx][nl];                    // X[m0+tx][n0+nl]
        const size_t off = (size_t)(n0 + nl) * NM + m0 + tx;
        __half h = __float2half_rn(v);
        g_XTh[off] = h;
        g_XTl[off] = __float2half_rn(v - __half2float(h));
    }
}

// W^T hi/lo (z = j-1)
__global__ void __launch_bounds__(256)
k_trW()
{
    const int z = blockIdx.z;
    const float* S = g_W32[z];
    __half* TH = g_WTh[z];
    __half* TL = g_WTl[z];
    __shared__ float t[32][33];
    const int tx = threadIdx.x, ty = threadIdx.y;
    const int n0 = blockIdx.x * 32, m0 = blockIdx.y * 32;
#pragma unroll
    for (int i = 0; i < 4; ++i)
        t[ty + 8 * i][tx] = S[(size_t)(m0 + ty + 8 * i) * NM + n0 + tx];
    __syncthreads();
#pragma unroll
    for (int i = 0; i < 4; ++i) {
        const int nl = ty + 8 * i;
        const float v = t[tx][nl];
        const size_t off = (size_t)(n0 + nl) * NM + m0 + tx;
        __half h = __float2half_rn(v);
        TH[off] = h;
        TL[off] = __float2half_rn(v - __half2float(h));
    }
}

// ----------------------------------------------------------------------------
// Final mix: out[o,m,n] = bias[o] + sum_t theta[t,o] * plane_t[m,n]
__global__ void __launch_bounds__(256)
k_mix(const float* __restrict__ x, const float* __restrict__ theta,
      const float* __restrict__ bias, float* __restrict__ out)
{
    __shared__ float sh_th[25 * OUTC];
    __shared__ float sh_b[OUTC];
    const int tid = threadIdx.x;
    for (int t = tid; t < 25 * OUTC; t += 256) sh_th[t] = theta[t];
    if (tid < OUTC) sh_b[tid] = bias[tid];
    __syncthreads();

    const int off = (blockIdx.x * 256 + tid) * 2;

    float2 v[25];
    v[0] = *(const float2*)(x + off);
#pragma unroll
    for (int j = 1; j <= 4; ++j) v[j] = *(const float2*)(g_W32[j - 1] + off);
#pragma unroll
    for (int i = 1; i <= 4; ++i) v[i * 5] = *(const float2*)(g_Y32[i - 1] + off);
#pragma unroll
    for (int i = 1; i <= 4; ++i)
#pragma unroll
        for (int j = 1; j <= 4; ++j)
            v[i * 5 + j] = *(const float2*)(g_Z32[(i - 1) * 4 + (j - 1)] + off);

#pragma unroll
    for (int o = 0; o < OUTC; ++o) {
        float sx = sh_b[o], sy = sh_b[o];
#pragma unroll
        for (int t = 0; t < 25; ++t) {
            const float w = sh_th[t * OUTC + o];
            sx += w * v[t].x;
            sy += w * v[t].y;
        }
        *(float2*)(out + (size_t)o * N2 + off) = make_float2(sx, sy);
    }
}

// ----------------------------------------------------------------------------
extern "C" void kernel_launch(void* const* d_in, const int* in_sizes, int n_in,
                              void* d_out, int out_size)
{
    const float* x     = (const float*)d_in[0];
    const float* Lr    = (const float*)d_in[1];
    const float* Lc    = (const float*)d_in[2];
    const float* theta = (const float*)d_in[3];
    const float* bias  = (const float*)d_in[4];
    float* out = (float*)d_out;

    cudaFuncSetAttribute(k_gemm_cheb, cudaFuncAttributeMaxDynamicSharedMemorySize, SMEM_DYN);
    cudaFuncSetAttribute(k_gemm_w,    cudaFuncAttributeMaxDynamicSharedMemorySize, SMEM_DYN);
    cudaFuncSetAttribute(k_gemm_y,    cudaFuncAttributeMaxDynamicSharedMemorySize, SMEM_DYN);
    cudaFuncSetAttribute(k_gemm_z,    cudaFuncAttributeMaxDynamicSharedMemorySize, SMEM_DYN);

    const dim3 blk(256);
    const dim3 g2(NM / 128, NM / 128, 1);        // (12,12)
    const dim3 blkT(32, 8);
    const dim3 gT(NM / 32, NM / 32, 1);

    // input conversions
    k_cvt<<<dim3(N2 / 1024, 1, 3), blk>>>(x, Lr, Lc);
    k_cvtT<<<gT, blkT>>>(x);

    // Chebyshev bases (sequential per side)
    for (int step = 0; step < 3; ++step)
        k_gemm_cheb<<<g2, blk, SMEM_DYN>>>(Lr, 0, step);
    for (int step = 0; step < 3; ++step)
        k_gemm_cheb<<<g2, blk, SMEM_DYN>>>(Lc, 1, step);

    // W_j = X @ Tc_j
    k_gemm_w<<<dim3(12, 12, 4), blk, SMEM_DYN>>>();
    // W^T hi/lo for the Z-stage B operands
    k_trW<<<dim3(NM / 32, NM / 32, 4), blkT>>>();
    // Y_i = Tr_i @ X
    k_gemm_y<<<dim3(12, 12, 4), blk, SMEM_DYN>>>();
    // Z_ij = Tr_i @ W_j
    k_gemm_z<<<dim3(12, 12, 16), blk, SMEM_DYN>>>();

    // final 25-term mix
    k_mix<<<N2 / 512, blk>>>(x, theta, bias, out);
}

// round 7
// speedup vs baseline: 2.2421x; 1.0282x over previous
#include <cuda_runtime.h>
#include <cuda_fp16.h>
#include <cstdint>

// ============================================================================
// BilinearChebConv via mma.sync (fp16 3-way split GEMMs, fp32 accumulate)
// out[o] = sum_{i,j} theta[i,j,o] * (Tr_i @ X @ Tc_j) + bias[o]
// M = N = 1536, orders 4/4, OUT = 32.
// R7: 512-thread CTA, 16 warps of 32x32 (4 warps/SMSP) to fill the tensor
// pipe's idle gaps; per-thread regs cut to fit 128-reg budget.
// ============================================================================

constexpr int NM   = 1536;
constexpr int N2   = NM * NM;
constexpr int OUTC = 32;

constexpr int BK    = 64;                 // k per stage (64 fp16 = 128B row)
constexpr int NKT   = NM / BK;            // 24
constexpr int PLANE = 128 * 128;          // bytes per operand plane per stage
constexpr int STAGE = 4 * PLANE;          // Ah|Al|Bh|Bl = 64 KB
constexpr unsigned SMEM_DYN = 3 * STAGE;  // 192 KB

// ----------------------------------------------------------------------------
// Scratch (no cudaMalloc allowed -> __device__ globals)
__device__ float g_Tr32[3][N2];
__device__ float g_Tc32[3][N2];
__device__ float g_W32[4][N2];          // W_j = X @ Tc_j      (= Z_{0,j})
__device__ float g_Y32[4][N2];          // Y_i = Tr_i @ X      (= Z_{i,0})
__device__ float g_Z32[16][N2];         // Z_ij = Tr_i @ W_j,  i,j = 1..4
// fp16 hi/lo operand planes (all B operands stored as N x K)
__device__ __half g_Xh[N2],  g_Xl[N2];      // X   (A operand, row-major)
__device__ __half g_XTh[N2], g_XTl[N2];     // X^T (B operand for Y-stage)
__device__ __half g_Lrh[N2], g_Lrl[N2];
__device__ __half g_Lch[N2], g_Lcl[N2];
__device__ __half g_Trh[3][N2], g_Trl[3][N2];   // symmetric -> B directly
__device__ __half g_Tch[3][N2], g_Tcl[3][N2];
__device__ __half g_WTh[4][N2], g_WTl[4][N2];   // W_j^T (B for Z-stage)

// ----------------------------------------------------------------------------
// PTX helpers (all baseline sm_80+ instructions)
// ----------------------------------------------------------------------------
__device__ __forceinline__ uint32_t smem_u32(const void* p) {
    uint32_t a;
    asm("{ .reg .u64 t; cvta.to.shared.u64 t, %1; cvt.u32.u64 %0, t; }"
        : "=r"(a) : "l"(p));
    return a;
}
__device__ __forceinline__ void cpa16(uint32_t s, const void* g) {
    asm volatile("cp.async.cg.shared.global [%0], [%1], 16;\n" :: "r"(s), "l"(g));
}
__device__ __forceinline__ void cp_commit() {
    asm volatile("cp.async.commit_group;\n" ::: "memory");
}
__device__ __forceinline__ void cp_wait2() {
    asm volatile("cp.async.wait_group 2;\n" ::: "memory");
}
__device__ __forceinline__ void ldsm4(uint32_t* r, uint32_t a) {
    asm volatile("ldmatrix.sync.aligned.m8n8.x4.shared.b16 {%0,%1,%2,%3}, [%4];"
                 : "=r"(r[0]), "=r"(r[1]), "=r"(r[2]), "=r"(r[3]) : "r"(a));
}
__device__ __forceinline__ void mma16816(float* c, const uint32_t* a,
                                         uint32_t b0, uint32_t b1) {
    asm volatile("mma.sync.aligned.m16n8k16.row.col.f32.f16.f16.f32 "
                 "{%0,%1,%2,%3}, {%4,%5,%6,%7}, {%8,%9}, {%0,%1,%2,%3};"
                 : "+f"(c[0]), "+f"(c[1]), "+f"(c[2]), "+f"(c[3])
                 : "r"(a[0]), "r"(a[1]), "r"(a[2]), "r"(a[3]), "r"(b0), "r"(b1));
}

extern __shared__ char dsm[];

// ----------------------------------------------------------------------------
// Core GEMM: C(128x128) += 3-split product over K=1536.
// Block = 512 threads, 16 warps of 32x32. acc[2][4][4] per thread.
// Smem rows are 128B with SW128 xor swizzle -> conflict-free ldmatrix.
// ----------------------------------------------------------------------------
__device__ __forceinline__ void gemm_main(
    const __half* __restrict__ Ah, const __half* __restrict__ Al,
    const __half* __restrict__ Bh, const __half* __restrict__ Bl,
    float (&acc)[2][4][4])
{
    const uint32_t sbase = smem_u32(dsm);
    const int tid = threadIdx.x, lane = tid & 31, wid = tid >> 5;
    const int wm = (wid & 3) * 32, wn = (wid >> 2) * 32;
    const int l15 = lane & 15, lhi = lane >> 4;
    const int bm = blockIdx.y * 128, bn = blockIdx.x * 128;
    const int lc = tid & 7, lr = tid >> 3;     // loader: chunk 0..7, row 0..63

    auto load_stage = [&](int st, int kc) {
        const uint32_t sb = sbase + st * STAGE;
#pragma unroll
        for (int rr = 0; rr < 128; rr += 64) {
            const int r = lr + rr;
            const uint32_t off = (uint32_t)(r * 128) + (uint32_t)((lc ^ (r & 7)) << 4);
            const size_t ga = (size_t)(bm + r) * NM + kc + lc * 8;
            const size_t gb = (size_t)(bn + r) * NM + kc + lc * 8;
            cpa16(sb + 0 * PLANE + off, Ah + ga);
            cpa16(sb + 1 * PLANE + off, Al + ga);
            cpa16(sb + 2 * PLANE + off, Bh + gb);
            cpa16(sb + 3 * PLANE + off, Bl + gb);
        }
    };

    load_stage(0, 0);      cp_commit();
    load_stage(1, BK);     cp_commit();
    load_stage(2, 2 * BK); cp_commit();

    for (int kt = 0; kt < NKT; ++kt) {
        cp_wait2();                 // stage kt resident (2 younger groups open)
        __syncthreads();
        const uint32_t sb = sbase + (kt % 3) * STAGE;
#pragma unroll
        for (int kh = 0; kh < 4; ++kh) {               // four k16 slices per stage
            uint32_t ahf[2][4], alf[2][4];
            const int chunkL = (kh << 1) | lhi;        // logical 16B chunk
#pragma unroll
            for (int mt = 0; mt < 2; ++mt) {
                const int r = wm + mt * 16 + l15;
                const uint32_t off = (uint32_t)(r * 128) +
                                     (uint32_t)((chunkL ^ (r & 7)) << 4);
                ldsm4(ahf[mt], sb + 0 * PLANE + off);
                ldsm4(alf[mt], sb + 1 * PLANE + off);
            }
#pragma unroll
            for (int g = 0; g < 2; ++g) {
                uint32_t bh4[4], bl4[4];
                const int r = wn + g * 16 + l15;
                const uint32_t off = (uint32_t)(r * 128) +
                                     (uint32_t)((chunkL ^ (r & 7)) << 4);
                ldsm4(bh4, sb + 2 * PLANE + off);
                ldsm4(bl4, sb + 3 * PLANE + off);
#pragma unroll
                for (int mt = 0; mt < 2; ++mt)
#pragma unroll
                    for (int j = 0; j < 2; ++j)
                        mma16816(acc[mt][g * 2 + j], ahf[mt], bh4[j], bh4[j + 2]);
#pragma unroll
                for (int mt = 0; mt < 2; ++mt)
#pragma unroll
                    for (int j = 0; j < 2; ++j)
                        mma16816(acc[mt][g * 2 + j], alf[mt], bh4[j], bh4[j + 2]);
#pragma unroll
                for (int mt = 0; mt < 2; ++mt)
#pragma unroll
                    for (int j = 0; j < 2; ++j)
                        mma16816(acc[mt][g * 2 + j], ahf[mt], bl4[j], bl4[j + 2]);
            }
        }
        __syncthreads();            // compute done before reloading this buffer
        if (kt + 3 < NKT) load_stage(kt % 3, (kt + 3) * BK);
        cp_commit();                // constant group accounting
    }
}

// plain fp32 epilogue -------------------------------------------------------
__device__ __forceinline__ void epi_plain(float (&acc)[2][4][4], float* __restrict__ C)
{
    const int tid = threadIdx.x, lane = tid & 31, wid = tid >> 5;
    const int wm = (wid & 3) * 32, wn = (wid >> 2) * 32;
    const int bm = blockIdx.y * 128, bn = blockIdx.x * 128;
    const int l4 = lane >> 2, l2 = (lane & 3) * 2;
#pragma unroll
    for (int mt = 0; mt < 2; ++mt)
#pragma unroll
        for (int h = 0; h < 2; ++h) {
            const int row = bm + wm + mt * 16 + l4 + h * 8;
#pragma unroll
            for (int nt = 0; nt < 4; ++nt) {
                const int col = bn + wn + nt * 8 + l2;
                *(float2*)(C + (size_t)row * NM + col) =
                    make_float2(acc[mt][nt][2 * h], acc[mt][nt][2 * h + 1]);
            }
        }
}

// ----------------------------------------------------------------------------
// Kernels
// ----------------------------------------------------------------------------

// Chebyshev step: T_step = 2 * L @ B - D. Writes fp32 + fp16 hi/lo (symmetric,
// so the row-major result doubles as the N x K B-operand).
__global__ void __launch_bounds__(512)
k_gemm_cheb(const float* __restrict__ L32, int side, int step)
{
    const __half* Ah = side ? g_Lch : g_Lrh;
    const __half* Al = side ? g_Lcl : g_Lrl;
    const __half* Bh = (step == 0) ? Ah : (side ? g_Tch[step - 1] : g_Trh[step - 1]);
    const __half* Bl = (step == 0) ? Al : (side ? g_Tcl[step - 1] : g_Trl[step - 1]);
    const float* D = (step == 0) ? nullptr
                   : (step == 1) ? L32
                   : (side ? g_Tc32[0] : g_Tr32[0]);
    float* C = side ? g_Tc32[step] : g_Tr32[step];
    __half* Ho = side ? g_Tch[step] : g_Trh[step];
    __half* Lo = side ? g_Tcl[step] : g_Trl[step];

    float acc[2][4][4] = {};
    gemm_main(Ah, Al, Bh, Bl, acc);

    const int tid = threadIdx.x, lane = tid & 31, wid = tid >> 5;
    const int wm = (wid & 3) * 32, wn = (wid >> 2) * 32;
    const int bm = blockIdx.y * 128, bn = blockIdx.x * 128;
    const int l4 = lane >> 2, l2 = (lane & 3) * 2;
#pragma unroll
    for (int mt = 0; mt < 2; ++mt)
#pragma unroll
        for (int h = 0; h < 2; ++h) {
            const int row = bm + wm + mt * 16 + l4 + h * 8;
#pragma unroll
            for (int nt = 0; nt < 4; ++nt) {
                const int col = bn + wn + nt * 8 + l2;
                const size_t off = (size_t)row * NM + col;
                float2 d;
                if (D) d = *(const float2*)(D + off);
                else   d = make_float2(row == col ? 1.f : 0.f,
                                       row == col + 1 ? 1.f : 0.f);
                const float vx = 2.f * acc[mt][nt][2 * h]     - d.x;
                const float vy = 2.f * acc[mt][nt][2 * h + 1] - d.y;
                *(float2*)(C + off) = make_float2(vx, vy);
                const __half hx = __float2half_rn(vx);
                const __half hy = __float2half_rn(vy);
                __half2 q;
                q.x = hx; q.y = hy;
                *(__half2*)(Ho + off) = q;
                q.x = __float2half_rn(vx - __half2float(hx));
                q.y = __float2half_rn(vy - __half2float(hy));
                *(__half2*)(Lo + off) = q;
            }
        }
}

// W_j = X @ Tc_j (j-1 = blockIdx.z); B symmetric.
__global__ void __launch_bounds__(512)
k_gemm_w()
{
    const int z = blockIdx.z;
    const __half* Bh = (z == 0) ? g_Lch : g_Tch[z - 1];
    const __half* Bl = (z == 0) ? g_Lcl : g_Tcl[z - 1];
    float acc[2][4][4] = {};
    gemm_main(g_Xh, g_Xl, Bh, Bl, acc);
    epi_plain(acc, g_W32[z]);
}

// Y_i = Tr_i @ X (i-1 = blockIdx.z); B = X^T planes.
__global__ void __launch_bounds__(512)
k_gemm_y()
{
    const int z = blockIdx.z;
    const __half* Ah = (z == 0) ? g_Lrh : g_Trh[z - 1];
    const __half* Al = (z == 0) ? g_Lrl : g_Trl[z - 1];
    float acc[2][4][4] = {};
    gemm_main(Ah, Al, g_XTh, g_XTl, acc);
    epi_plain(acc, g_Y32[z]);
}

// Z_ij = Tr_i @ W_j; z = (i-1)*4 + (j-1); B = W_j^T planes.
__global__ void __launch_bounds__(512)
k_gemm_z()
{
    const int z = blockIdx.z;
    const int i = z >> 2, j = z & 3;
    const __half* Ah = (i == 0) ? g_Lrh : g_Trh[i - 1];
    const __half* Al = (i == 0) ? g_Lrl : g_Trl[i - 1];
    float acc[2][4][4] = {};
    gemm_main(Ah, Al, g_WTh[j], g_WTl[j], acc);
    epi_plain(acc, g_Z32[z]);
}

// ----------------------------------------------------------------------------
// fp32 -> fp16 hi/lo conversion of inputs (z: 0=X, 1=Lr, 2=Lc)
__global__ void __launch_bounds__(256)
k_cvt(const float* __restrict__ x, const float* __restrict__ Lr,
      const float* __restrict__ Lc)
{
    const int zz = blockIdx.z;
    const float* s = (zz == 0) ? x : (zz == 1) ? Lr : Lc;
    __half* H = (zz == 0) ? g_Xh : (zz == 1) ? g_Lrh : g_Lch;
    __half* L = (zz == 0) ? g_Xl : (zz == 1) ? g_Lrl : g_Lcl;
    const int i = (blockIdx.x * 256 + threadIdx.x) * 4;
    float4 v = *(const float4*)(s + i);
    __half h0 = __float2half_rn(v.x), h1 = __float2half_rn(v.y);
    __half h2 = __float2half_rn(v.z), h3 = __float2half_rn(v.w);
    __half2 p;
    p.x = h0; p.y = h1; *(__half2*)(H + i)     = p;
    p.x = h2; p.y = h3; *(__half2*)(H + i + 2) = p;
    p.x = __float2half_rn(v.x - __half2float(h0));
    p.y = __float2half_rn(v.y - __half2float(h1));
    *(__half2*)(L + i) = p;
    p.x = __float2half_rn(v.z - __half2float(h2));
    p.y = __float2half_rn(v.w - __half2float(h3));
    *(__half2*)(L + i + 2) = p;
}

// X^T hi/lo
__global__ void __launch_bounds__(256)
k_cvtT(const float* __restrict__ X)
{
    __shared__ float t[32][33];
    const int tx = threadIdx.x, ty = threadIdx.y;
    const int n0 = blockIdx.x * 32, m0 = blockIdx.y * 32;
#pragma unroll
    for (int i = 0; i < 4; ++i)
        t[ty + 8 * i][tx] = X[(size_t)(m0 + ty + 8 * i) * NM + n0 + tx];
    __syncthreads();
#pragma unroll
    for (int i = 0; i < 4; ++i) {
        const int nl = ty + 8 * i;
        const float v = t[tx][nl];                    // X[m0+tx][n0+nl]
        const size_t off = (size_t)(n0 + nl) * NM + m0 + tx;
        __half h = __float2half_rn(v);
        g_XTh[off] = h;
        g_XTl[off] = __float2half_rn(v - __half2float(h));
    }
}

// W^T hi/lo (z = j-1)
__global__ void __launch_bounds__(256)
k_trW()
{
    const int z = blockIdx.z;
    const float* S = g_W32[z];
    __half* TH = g_WTh[z];
    __half* TL = g_WTl[z];
    __shared__ float t[32][33];
    const int tx = threadIdx.x, ty = threadIdx.y;
    const int n0 = blockIdx.x * 32, m0 = blockIdx.y * 32;
#pragma unroll
    for (int i = 0; i < 4; ++i)
        t[ty + 8 * i][tx] = S[(size_t)(m0 + ty + 8 * i) * NM + n0 + tx];
    __syncthreads();
#pragma unroll
    for (int i = 0; i < 4; ++i) {
        const int nl = ty + 8 * i;
        const float v = t[tx][nl];
        const size_t off = (size_t)(n0 + nl) * NM + m0 + tx;
        __half h = __float2half_rn(v);
        TH[off] = h;
        TL[off] = __float2half_rn(v - __half2float(h));
    }
}

// ----------------------------------------------------------------------------
// Final mix: out[o,m,n] = bias[o] + sum_t theta[t,o] * plane_t[m,n]
__global__ void __launch_bounds__(256)
k_mix(const float* __restrict__ x, const float* __restrict__ theta,
      const float* __restrict__ bias, float* __restrict__ out)
{
    __shared__ float sh_th[25 * OUTC];
    __shared__ float sh_b[OUTC];
    const int tid = threadIdx.x;
    for (int t = tid; t < 25 * OUTC; t += 256) sh_th[t] = theta[t];
    if (tid < OUTC) sh_b[tid] = bias[tid];
    __syncthreads();

    const int off = (blockIdx.x * 256 + tid) * 2;

    float2 v[25];
    v[0] = *(const float2*)(x + off);
#pragma unroll
    for (int j = 1; j <= 4; ++j) v[j] = *(const float2*)(g_W32[j - 1] + off);
#pragma unroll
    for (int i = 1; i <= 4; ++i) v[i * 5] = *(const float2*)(g_Y32[i - 1] + off);
#pragma unroll
    for (int i = 1; i <= 4; ++i)
#pragma unroll
        for (int j = 1; j <= 4; ++j)
            v[i * 5 + j] = *(const float2*)(g_Z32[(i - 1) * 4 + (j - 1)] + off);

#pragma unroll
    for (int o = 0; o < OUTC; ++o) {
        float sx = sh_b[o], sy = sh_b[o];
#pragma unroll
        for (int t = 0; t < 25; ++t) {
            const float w = sh_th[t * OUTC + o];
            sx += w * v[t].x;
            sy += w * v[t].y;
        }
        *(float2*)(out + (size_t)o * N2 + off) = make_float2(sx, sy);
    }
}

// ----------------------------------------------------------------------------
extern "C" void kernel_launch(void* const* d_in, const int* in_sizes, int n_in,
                              void* d_out, int out_size)
{
    const float* x     = (const float*)d_in[0];
    const float* Lr    = (const float*)d_in[1];
    const float* Lc    = (const float*)d_in[2];
    const float* theta = (const float*)d_in[3];
    const float* bias  = (const float*)d_in[4];
    float* out = (float*)d_out;

    cudaFuncSetAttribute(k_gemm_cheb, cudaFuncAttributeMaxDynamicSharedMemorySize, SMEM_DYN);
    cudaFuncSetAttribute(k_gemm_w,    cudaFuncAttributeMaxDynamicSharedMemorySize, SMEM_DYN);
    cudaFuncSetAttribute(k_gemm_y,    cudaFuncAttributeMaxDynamicSharedMemorySize, SMEM_DYN);
    cudaFuncSetAttribute(k_gemm_z,    cudaFuncAttributeMaxDynamicSharedMemorySize, SMEM_DYN);

    const dim3 blk(512);
    const dim3 g2(NM / 128, NM / 128, 1);        // (12,12)
    const dim3 blkT(32, 8);
    const dim3 gT(NM / 32, NM / 32, 1);

    // input conversions
    k_cvt<<<dim3(N2 / 1024, 1, 3), 256>>>(x, Lr, Lc);
    k_cvtT<<<gT, blkT>>>(x);

    // Chebyshev bases (sequential per side)
    for (int step = 0; step < 3; ++step)
        k_gemm_cheb<<<g2, blk, SMEM_DYN>>>(Lr, 0, step);
    for (int step = 0; step < 3; ++step)
        k_gemm_cheb<<<g2, blk, SMEM_DYN>>>(Lc, 1, step);

    // W_j = X @ Tc_j
    k_gemm_w<<<dim3(12, 12, 4), blk, SMEM_DYN>>>();
    // W^T hi/lo for the Z-stage B operands
    k_trW<<<dim3(NM / 32, NM / 32, 4), blkT>>>();
    // Y_i = Tr_i @ X
    k_gemm_y<<<dim3(12, 12, 4), blk, SMEM_DYN>>>();
    // Z_ij = Tr_i @ W_j
    k_gemm_z<<<dim3(12, 12, 16), blk, SMEM_DYN>>>();

    // final 25-term mix
    k_mix<<<N2 / 512, 256>>>(x, theta, bias, out);
}

// round 8
// speedup vs baseline: 2.2434x; 1.0006x over previous
#include <cuda_runtime.h>
#include <cuda_fp16.h>
#include <cstdint>

// ============================================================================
// BilinearChebConv via mma.sync (fp16 3-way split GEMMs, fp32 accumulate)
// out[o] = sum_{i,j} theta[i,j,o] * (Tr_i @ X @ Tc_j) + bias[o]
// M = N = 1536, orders 4/4, OUT = 32.
// R8: R7 (512 threads, 16 warps of 32x32) + double-buffered register
// fragments: prefetch k16-slice kh+1's ldmatrix while kh's MMAs run, so the
// L1 phase hides under the tensor phase instead of serializing with it.
// ============================================================================

constexpr int NM   = 1536;
constexpr int N2   = NM * NM;
constexpr int OUTC = 32;

constexpr int BK    = 64;                 // k per stage (64 fp16 = 128B row)
constexpr int NKT   = NM / BK;            // 24
constexpr int PLANE = 128 * 128;          // bytes per operand plane per stage
constexpr int STAGE = 4 * PLANE;          // Ah|Al|Bh|Bl = 64 KB
constexpr unsigned SMEM_DYN = 3 * STAGE;  // 192 KB

// ----------------------------------------------------------------------------
// Scratch (no cudaMalloc allowed -> __device__ globals)
__device__ float g_Tr32[3][N2];
__device__ float g_Tc32[3][N2];
__device__ float g_W32[4][N2];          // W_j = X @ Tc_j      (= Z_{0,j})
__device__ float g_Y32[4][N2];          // Y_i = Tr_i @ X      (= Z_{i,0})
__device__ float g_Z32[16][N2];         // Z_ij = Tr_i @ W_j,  i,j = 1..4
// fp16 hi/lo operand planes (all B operands stored as N x K)
__device__ __half g_Xh[N2],  g_Xl[N2];      // X   (A operand, row-major)
__device__ __half g_XTh[N2], g_XTl[N2];     // X^T (B operand for Y-stage)
__device__ __half g_Lrh[N2], g_Lrl[N2];
__device__ __half g_Lch[N2], g_Lcl[N2];
__device__ __half g_Trh[3][N2], g_Trl[3][N2];   // symmetric -> B directly
__device__ __half g_Tch[3][N2], g_Tcl[3][N2];
__device__ __half g_WTh[4][N2], g_WTl[4][N2];   // W_j^T (B for Z-stage)

// ----------------------------------------------------------------------------
// PTX helpers (all baseline sm_80+ instructions)
// ----------------------------------------------------------------------------
__device__ __forceinline__ uint32_t smem_u32(const void* p) {
    uint32_t a;
    asm("{ .reg .u64 t; cvta.to.shared.u64 t, %1; cvt.u32.u64 %0, t; }"
        : "=r"(a) : "l"(p));
    return a;
}
__device__ __forceinline__ void cpa16(uint32_t s, const void* g) {
    asm volatile("cp.async.cg.shared.global [%0], [%1], 16;\n" :: "r"(s), "l"(g));
}
__device__ __forceinline__ void cp_commit() {
    asm volatile("cp.async.commit_group;\n" ::: "memory");
}
__device__ __forceinline__ void cp_wait2() {
    asm volatile("cp.async.wait_group 2;\n" ::: "memory");
}
__device__ __forceinline__ void ldsm4(uint32_t* r, uint32_t a) {
    asm volatile("ldmatrix.sync.aligned.m8n8.x4.shared.b16 {%0,%1,%2,%3}, [%4];"
                 : "=r"(r[0]), "=r"(r[1]), "=r"(r[2]), "=r"(r[3]) : "r"(a));
}
__device__ __forceinline__ void mma16816(float* c, const uint32_t* a,
                                         uint32_t b0, uint32_t b1) {
    asm volatile("mma.sync.aligned.m16n8k16.row.col.f32.f16.f16.f32 "
                 "{%0,%1,%2,%3}, {%4,%5,%6,%7}, {%8,%9}, {%0,%1,%2,%3};"
                 : "+f"(c[0]), "+f"(c[1]), "+f"(c[2]), "+f"(c[3])
                 : "r"(a[0]), "r"(a[1]), "r"(a[2]), "r"(a[3]), "r"(b0), "r"(b1));
}

extern __shared__ char dsm[];

// ----------------------------------------------------------------------------
// Core GEMM: C(128x128) += 3-split product over K=1536.
// Block = 512 threads, 16 warps of 32x32. acc[2][4][4] per thread.
// Register fragments double-buffered across k16 slices.
// ----------------------------------------------------------------------------
__device__ __forceinline__ void gemm_main(
    const __half* __restrict__ Ah, const __half* __restrict__ Al,
    const __half* __restrict__ Bh, const __half* __restrict__ Bl,
    float (&acc)[2][4][4])
{
    const uint32_t sbase = smem_u32(dsm);
    const int tid = threadIdx.x, lane = tid & 31, wid = tid >> 5;
    const int wm = (wid & 3) * 32, wn = (wid >> 2) * 32;
    const int l15 = lane & 15, lhi = lane >> 4;
    const int bm = blockIdx.y * 128, bn = blockIdx.x * 128;
    const int lc = tid & 7, lr = tid >> 3;     // loader: chunk 0..7, row 0..63

    auto load_stage = [&](int st, int kc) {
        const uint32_t sb = sbase + st * STAGE;
#pragma unroll
        for (int rr = 0; rr < 128; rr += 64) {
            const int r = lr + rr;
            const uint32_t off = (uint32_t)(r * 128) + (uint32_t)((lc ^ (r & 7)) << 4);
            const size_t ga = (size_t)(bm + r) * NM + kc + lc * 8;
            const size_t gb = (size_t)(bn + r) * NM + kc + lc * 8;
            cpa16(sb + 0 * PLANE + off, Ah + ga);
            cpa16(sb + 1 * PLANE + off, Al + ga);
            cpa16(sb + 2 * PLANE + off, Bh + gb);
            cpa16(sb + 3 * PLANE + off, Bl + gb);
        }
    };

    load_stage(0, 0);      cp_commit();
    load_stage(1, BK);     cp_commit();
    load_stage(2, 2 * BK); cp_commit();

    // double-buffered register fragments: [buf][mt or g][4]
    uint32_t fah[2][2][4], fal[2][2][4], fbh[2][2][4], fbl[2][2][4];

    // fragment loader for k16 slice kh of the stage at smem base sb
    auto ldfrag = [&](uint32_t sb, int kh, int buf) {
        const int chunkL = (kh << 1) | lhi;
#pragma unroll
        for (int mt = 0; mt < 2; ++mt) {
            const int r = wm + mt * 16 + l15;
            const uint32_t off = (uint32_t)(r * 128) +
                                 (uint32_t)((chunkL ^ (r & 7)) << 4);
            ldsm4(fah[buf][mt], sb + 0 * PLANE + off);
            ldsm4(fal[buf][mt], sb + 1 * PLANE + off);
        }
#pragma unroll
        for (int g = 0; g < 2; ++g) {
            const int r = wn + g * 16 + l15;
            const uint32_t off = (uint32_t)(r * 128) +
                                 (uint32_t)((chunkL ^ (r & 7)) << 4);
            ldsm4(fbh[buf][g], sb + 2 * PLANE + off);
            ldsm4(fbl[buf][g], sb + 3 * PLANE + off);
        }
    };

    for (int kt = 0; kt < NKT; ++kt) {
        cp_wait2();                 // stage kt resident (2 younger groups open)
        __syncthreads();
        const uint32_t sb = sbase + (kt % 3) * STAGE;
        ldfrag(sb, 0, 0);           // preload slice 0
#pragma unroll
        for (int kh = 0; kh < 4; ++kh) {
            const int cur = kh & 1, nxt = cur ^ 1;
            if (kh < 3) ldfrag(sb, kh + 1, nxt);   // prefetch next slice
            // MMAs on cur overlap the in-flight ldsm of nxt
#pragma unroll
            for (int mt = 0; mt < 2; ++mt)
#pragma unroll
                for (int g = 0; g < 2; ++g)
#pragma unroll
                    for (int j = 0; j < 2; ++j)
                        mma16816(acc[mt][g * 2 + j], fah[cur][mt],
                                 fbh[cur][g][j], fbh[cur][g][j + 2]);
#pragma unroll
            for (int mt = 0; mt < 2; ++mt)
#pragma unroll
                for (int g = 0; g < 2; ++g)
#pragma unroll
                    for (int j = 0; j < 2; ++j)
                        mma16816(acc[mt][g * 2 + j], fal[cur][mt],
                                 fbh[cur][g][j], fbh[cur][g][j + 2]);
#pragma unroll
            for (int mt = 0; mt < 2; ++mt)
#pragma unroll
                for (int g = 0; g < 2; ++g)
#pragma unroll
                    for (int j = 0; j < 2; ++j)
                        mma16816(acc[mt][g * 2 + j], fah[cur][mt],
                                 fbl[cur][g][j], fbl[cur][g][j + 2]);
        }
        __syncthreads();            // compute done before reloading this buffer
        if (kt + 3 < NKT) load_stage(kt % 3, (kt + 3) * BK);
        cp_commit();                // constant group accounting
    }
}

// plain fp32 epilogue -------------------------------------------------------
__device__ __forceinline__ void epi_plain(float (&acc)[2][4][4], float* __restrict__ C)
{
    const int tid = threadIdx.x, lane = tid & 31, wid = tid >> 5;
    const int wm = (wid & 3) * 32, wn = (wid >> 2) * 32;
    const int bm = blockIdx.y * 128, bn = blockIdx.x * 128;
    const int l4 = lane >> 2, l2 = (lane & 3) * 2;
#pragma unroll
    for (int mt = 0; mt < 2; ++mt)
#pragma unroll
        for (int h = 0; h < 2; ++h) {
            const int row = bm + wm + mt * 16 + l4 + h * 8;
#pragma unroll
            for (int nt = 0; nt < 4; ++nt) {
                const int col = bn + wn + nt * 8 + l2;
                *(float2*)(C + (size_t)row * NM + col) =
                    make_float2(acc[mt][nt][2 * h], acc[mt][nt][2 * h + 1]);
            }
        }
}

// ----------------------------------------------------------------------------
// Kernels
// ----------------------------------------------------------------------------

// Chebyshev step: T_step = 2 * L @ B - D. Writes fp32 + fp16 hi/lo (symmetric,
// so the row-major result doubles as the N x K B-operand).
__global__ void __launch_bounds__(512)
k_gemm_cheb(const float* __restrict__ L32, int side, int step)
{
    const __half* Ah = side ? g_Lch : g_Lrh;
    const __half* Al = side ? g_Lcl : g_Lrl;
    const __half* Bh = (step == 0) ? Ah : (side ? g_Tch[step - 1] : g_Trh[step - 1]);
    const __half* Bl = (step == 0) ? Al : (side ? g_Tcl[step - 1] : g_Trl[step - 1]);
    const float* D = (step == 0) ? nullptr
                   : (step == 1) ? L32
                   : (side ? g_Tc32[0] : g_Tr32[0]);
    float* C = side ? g_Tc32[step] : g_Tr32[step];
    __half* Ho = side ? g_Tch[step] : g_Trh[step];
    __half* Lo = side ? g_Tcl[step] : g_Trl[step];

    float acc[2][4][4] = {};
    gemm_main(Ah, Al, Bh, Bl, acc);

    const int tid = threadIdx.x, lane = tid & 31, wid = tid >> 5;
    const int wm = (wid & 3) * 32, wn = (wid >> 2) * 32;
    const int bm = blockIdx.y * 128, bn = blockIdx.x * 128;
    const int l4 = lane >> 2, l2 = (lane & 3) * 2;
#pragma unroll
    for (int mt = 0; mt < 2; ++mt)
#pragma unroll
        for (int h = 0; h < 2; ++h) {
            const int row = bm + wm + mt * 16 + l4 + h * 8;
#pragma unroll
            for (int nt = 0; nt < 4; ++nt) {
                const int col = bn + wn + nt * 8 + l2;
                const size_t off = (size_t)row * NM + col;
                float2 d;
                if (D) d = *(const float2*)(D + off);
                else   d = make_float2(row == col ? 1.f : 0.f,
                                       row == col + 1 ? 1.f : 0.f);
                const float vx = 2.f * acc[mt][nt][2 * h]     - d.x;
                const float vy = 2.f * acc[mt][nt][2 * h + 1] - d.y;
                *(float2*)(C + off) = make_float2(vx, vy);
                const __half hx = __float2half_rn(vx);
                const __half hy = __float2half_rn(vy);
                __half2 q;
                q.x = hx; q.y = hy;
                *(__half2*)(Ho + off) = q;
                q.x = __float2half_rn(vx - __half2float(hx));
                q.y = __float2half_rn(vy - __half2float(hy));
                *(__half2*)(Lo + off) = q;
            }
        }
}

// W_j = X @ Tc_j (j-1 = blockIdx.z); B symmetric.
__global__ void __launch_bounds__(512)
k_gemm_w()
{
    const int z = blockIdx.z;
    const __half* Bh = (z == 0) ? g_Lch : g_Tch[z - 1];
    const __half* Bl = (z == 0) ? g_Lcl : g_Tcl[z - 1];
    float acc[2][4][4] = {};
    gemm_main(g_Xh, g_Xl, Bh, Bl, acc);
    epi_plain(acc, g_W32[z]);
}

// Y_i = Tr_i @ X (i-1 = blockIdx.z); B = X^T planes.
__global__ void __launch_bounds__(512)
k_gemm_y()
{
    const int z = blockIdx.z;
    const __half* Ah = (z == 0) ? g_Lrh : g_Trh[z - 1];
    const __half* Al = (z == 0) ? g_Lrl : g_Trl[z - 1];
    float acc[2][4][4] = {};
    gemm_main(Ah, Al, g_XTh, g_XTl, acc);
    epi_plain(acc, g_Y32[z]);
}

// Z_ij = Tr_i @ W_j; z = (i-1)*4 + (j-1); B = W_j^T planes.
__global__ void __launch_bounds__(512)
k_gemm_z()
{
    const int z = blockIdx.z;
    const int i = z >> 2, j = z & 3;
    const __half* Ah = (i == 0) ? g_Lrh : g_Trh[i - 1];
    const __half* Al = (i == 0) ? g_Lrl : g_Trl[i - 1];
    float acc[2][4][4] = {};
    gemm_main(Ah, Al, g_WTh[j], g_WTl[j], acc);
    epi_plain(acc, g_Z32[z]);
}

// ----------------------------------------------------------------------------
// fp32 -> fp16 hi/lo conversion of inputs (z: 0=X, 1=Lr, 2=Lc)
__global__ void __launch_bounds__(256)
k_cvt(const float* __restrict__ x, const float* __restrict__ Lr,
      const float* __restrict__ Lc)
{
    const int zz = blockIdx.z;
    const float* s = (zz == 0) ? x : (zz == 1) ? Lr : Lc;
    __half* H = (zz == 0) ? g_Xh : (zz == 1) ? g_Lrh : g_Lch;
    __half* L = (zz == 0) ? g_Xl : (zz == 1) ? g_Lrl : g_Lcl;
    const int i = (blockIdx.x * 256 + threadIdx.x) * 4;
    float4 v = *(const float4*)(s + i);
    __half h0 = __float2half_rn(v.x), h1 = __float2half_rn(v.y);
    __half h2 = __float2half_rn(v.z), h3 = __float2half_rn(v.w);
    __half2 p;
    p.x = h0; p.y = h1; *(__half2*)(H + i)     = p;
    p.x = h2; p.y = h3; *(__half2*)(H + i + 2) = p;
    p.x = __float2half_rn(v.x - __half2float(h0));
    p.y = __float2half_rn(v.y - __half2float(h1));
    *(__half2*)(L + i) = p;
    p.x = __float2half_rn(v.z - __half2float(h2));
    p.y = __float2half_rn(v.w - __half2float(h3));
    *(__half2*)(L + i + 2) = p;
}

// X^T hi/lo
__global__ void __launch_bounds__(256)
k_cvtT(const float* __restrict__ X)
{
    __shared__ float t[32][33];
    const int tx = threadIdx.x, ty = threadIdx.y;
    const int n0 = blockIdx.x * 32, m0 = blockIdx.y * 32;
#pragma unroll
    for (int i = 0; i < 4; ++i)
        t[ty + 8 * i][tx] = X[(size_t)(m0 + ty + 8 * i) * NM + n0 + tx];
    __syncthreads();
#pragma unroll
    for (int i = 0; i < 4; ++i) {
        const int nl = ty + 8 * i;
        const float v = t[tx][nl];                    // X[m0+tx][n0+nl]
        const size_t off = (size_t)(n0 + nl) * NM + m0 + tx;
        __half h = __float2half_rn(v);
        g_XTh[off] = h;
        g_XTl[off] = __float2half_rn(v - __half2float(h));
    }
}

// W^T hi/lo (z = j-1)
__global__ void __launch_bounds__(256)
k_trW()
{
    const int z = blockIdx.z;
    const float* S = g_W32[z];
    __half* TH = g_WTh[z];
    __half* TL = g_WTl[z];
    __shared__ float t[32][33];
    const int tx = threadIdx.x, ty = threadIdx.y;
    const int n0 = blockIdx.x * 32, m0 = blockIdx.y * 32;
#pragma unroll
    for (int i = 0; i < 4; ++i)
        t[ty + 8 * i][tx] = S[(size_t)(m0 + ty + 8 * i) * NM + n0 + tx];
    __syncthreads();
#pragma unroll
    for (int i = 0; i < 4; ++i) {
        const int nl = ty + 8 * i;
        const float v = t[tx][nl];
        const size_t off = (size_t)(n0 + nl) * NM + m0 + tx;
        __half h = __float2half_rn(v);
        TH[off] = h;
        TL[off] = __float2half_rn(v - __half2float(h));
    }
}

// ----------------------------------------------------------------------------
// Final mix: out[o,m,n] = bias[o] + sum_t theta[t,o] * plane_t[m,n]
__global__ void __launch_bounds__(256)
k_mix(const float* __restrict__ x, const float* __restrict__ theta,
      const float* __restrict__ bias, float* __restrict__ out)
{
    __shared__ float sh_th[25 * OUTC];
    __shared__ float sh_b[OUTC];
    const int tid = threadIdx.x;
    for (int t = tid; t < 25 * OUTC; t += 256) sh_th[t] = theta[t];
    if (tid < OUTC) sh_b[tid] = bias[tid];
    __syncthreads();

    const int off = (blockIdx.x * 256 + tid) * 2;

    float2 v[25];
    v[0] = *(const float2*)(x + off);
#pragma unroll
    for (int j = 1; j <= 4; ++j) v[j] = *(const float2*)(g_W32[j - 1] + off);
#pragma unroll
    for (int i = 1; i <= 4; ++i) v[i * 5] = *(const float2*)(g_Y32[i - 1] + off);
#pragma unroll
    for (int i = 1; i <= 4; ++i)
#pragma unroll
        for (int j = 1; j <= 4; ++j)
            v[i * 5 + j] = *(const float2*)(g_Z32[(i - 1) * 4 + (j - 1)] + off);

#pragma unroll
    for (int o = 0; o < OUTC; ++o) {
        float sx = sh_b[o], sy = sh_b[o];
#pragma unroll
        for (int t = 0; t < 25; ++t) {
            const float w = sh_th[t * OUTC + o];
            sx += w * v[t].x;
            sy += w * v[t].y;
        }
        *(float2*)(out + (size_t)o * N2 + off) = make_float2(sx, sy);
    }
}

// ----------------------------------------------------------------------------
extern "C" void kernel_launch(void* const* d_in, const int* in_sizes, int n_in,
                              void* d_out, int out_size)
{
    const float* x     = (const float*)d_in[0];
    const float* Lr    = (const float*)d_in[1];
    const float* Lc    = (const float*)d_in[2];
    const float* theta = (const float*)d_in[3];
    const float* bias  = (const float*)d_in[4];
    float* out = (float*)d_out;

    cudaFuncSetAttribute(k_gemm_cheb, cudaFuncAttributeMaxDynamicSharedMemorySize, SMEM_DYN);
    cudaFuncSetAttribute(k_gemm_w,    cudaFuncAttributeMaxDynamicSharedMemorySize, SMEM_DYN);
    cudaFuncSetAttribute(k_gemm_y,    cudaFuncAttributeMaxDynamicSharedMemorySize, SMEM_DYN);
    cudaFuncSetAttribute(k_gemm_z,    cudaFuncAttributeMaxDynamicSharedMemorySize, SMEM_DYN);

    const dim3 blk(512);
    const dim3 g2(NM / 128, NM / 128, 1);        // (12,12)
    const dim3 blkT(32, 8);
    const dim3 gT(NM / 32, NM / 32, 1);

    // input conversions
    k_cvt<<<dim3(N2 / 1024, 1, 3), 256>>>(x, Lr, Lc);
    k_cvtT<<<gT, blkT>>>(x);

    // Chebyshev bases (sequential per side)
    for (int step = 0; step < 3; ++step)
        k_gemm_cheb<<<g2, blk, SMEM_DYN>>>(Lr, 0, step);
    for (int step = 0; step < 3; ++step)
        k_gemm_cheb<<<g2, blk, SMEM_DYN>>>(Lc, 1, step);

    // W_j = X @ Tc_j
    k_gemm_w<<<dim3(12, 12, 4), blk, SMEM_DYN>>>();
    // W^T hi/lo for the Z-stage B operands
    k_trW<<<dim3(NM / 32, NM / 32, 4), blkT>>>();
    // Y_i = Tr_i @ X
    k_gemm_y<<<dim3(12, 12, 4), blk, SMEM_DYN>>>();
    // Z_ij = Tr_i @ W_j
    k_gemm_z<<<dim3(12, 12, 16), blk, SMEM_DYN>>>();

    // final 25-term mix
    k_mix<<<N2 / 512, 256>>>(x, theta, bias, out);
}

// round 10
// speedup vs baseline: 2.6656x; 1.1882x over previous
#include <cuda_runtime.h>
#include <cuda_fp16.h>
#include <cstdint>

// ============================================================================
// BilinearChebConv via mma.sync (fp16 split GEMMs, fp32 accumulate)
// out[o] = sum_{i,j} theta[i,j,o] * (Tr_i @ X @ Tc_j) + bias[o]
// M = N = 1536, orders 4/4, OUT = 32.
// R10 = R9 resubmit (infra failure last round; kernel never ran).
// mma.sync tensor-active pins at ~53% regardless of schedule -> reduce
// MMA count. Terminal-stage GEMMs (Y, Z: 20 of 30) switch to 2-term split
// (AhBh + AlBh, B rounded to fp16): error ~1.2e-4 lands directly in output
// (no downstream amplification). Chain stages (cheb, W) stay 3-term.
// 2-term path drops the Bl smem plane entirely (48KB stages, -25% ldsm).
// ============================================================================

constexpr int NM   = 1536;
constexpr int N2   = NM * NM;
constexpr int OUTC = 32;

constexpr int BK     = 64;                  // k per stage (64 fp16 = 128B row)
constexpr int NKT    = NM / BK;             // 24
constexpr int PLANE  = 128 * 128;           // bytes per operand plane per stage
constexpr int STAGE3 = 4 * PLANE;           // Ah|Al|Bh|Bl = 64 KB (3-term)
constexpr int STAGE2 = 3 * PLANE;           // Ah|Al|Bh    = 48 KB (2-term)
constexpr unsigned SMEM_DYN3 = 3 * STAGE3;  // 192 KB
constexpr unsigned SMEM_DYN2 = 3 * STAGE2;  // 144 KB

// ----------------------------------------------------------------------------
// Scratch (no cudaMalloc allowed -> __device__ globals)
__device__ float g_Tr32[3][N2];
__device__ float g_Tc32[3][N2];
__device__ float g_W32[4][N2];          // W_j = X @ Tc_j      (= Z_{0,j})
__device__ float g_Y32[4][N2];          // Y_i = Tr_i @ X      (= Z_{i,0})
__device__ float g_Z32[16][N2];         // Z_ij = Tr_i @ W_j,  i,j = 1..4
// fp16 hi/lo operand planes (all B operands stored as N x K)
__device__ __half g_Xh[N2],  g_Xl[N2];      // X   (A operand, row-major)
__device__ __half g_XTh[N2];                // X^T hi (B for Y-stage, 2-term)
__device__ __half g_Lrh[N2], g_Lrl[N2];
__device__ __half g_Lch[N2], g_Lcl[N2];
__device__ __half g_Trh[3][N2], g_Trl[3][N2];   // symmetric -> B directly
__device__ __half g_Tch[3][N2], g_Tcl[3][N2];
__device__ __half g_WTh[4][N2];                 // W_j^T hi (B for Z, 2-term)

// ----------------------------------------------------------------------------
// PTX helpers (all baseline sm_80+ instructions)
// ----------------------------------------------------------------------------
__device__ __forceinline__ uint32_t smem_u32(const void* p) {
    uint32_t a;
    asm("{ .reg .u64 t; cvta.to.shared.u64 t, %1; cvt.u32.u64 %0, t; }"
        : "=r"(a) : "l"(p));
    return a;
}
__device__ __forceinline__ void cpa16(uint32_t s, const void* g) {
    asm volatile("cp.async.cg.shared.global [%0], [%1], 16;\n" :: "r"(s), "l"(g));
}
__device__ __forceinline__ void cp_commit() {
    asm volatile("cp.async.commit_group;\n" ::: "memory");
}
__device__ __forceinline__ void cp_wait2() {
    asm volatile("cp.async.wait_group 2;\n" ::: "memory");
}
__device__ __forceinline__ void ldsm4(uint32_t* r, uint32_t a) {
    asm volatile("ldmatrix.sync.aligned.m8n8.x4.shared.b16 {%0,%1,%2,%3}, [%4];"
                 : "=r"(r[0]), "=r"(r[1]), "=r"(r[2]), "=r"(r[3]) : "r"(a));
}
__device__ __forceinline__ void mma16816(float* c, const uint32_t* a,
                                         uint32_t b0, uint32_t b1) {
    asm volatile("mma.sync.aligned.m16n8k16.row.col.f32.f16.f16.f32 "
                 "{%0,%1,%2,%3}, {%4,%5,%6,%7}, {%8,%9}, {%0,%1,%2,%3};"
                 : "+f"(c[0]), "+f"(c[1]), "+f"(c[2]), "+f"(c[3])
                 : "r"(a[0]), "r"(a[1]), "r"(a[2]), "r"(a[3]), "r"(b0), "r"(b1));
}

extern __shared__ char dsm[];

// ----------------------------------------------------------------------------
// 3-term core GEMM: C(128x128) += (AhBh + AlBh + AhBl) over K=1536.
// Block = 512 threads, 16 warps of 32x32. acc[2][4][4] per thread.
// ----------------------------------------------------------------------------
__device__ __forceinline__ void gemm_main3(
    const __half* __restrict__ Ah, const __half* __restrict__ Al,
    const __half* __restrict__ Bh, const __half* __restrict__ Bl,
    float (&acc)[2][4][4])
{
    const uint32_t sbase = smem_u32(dsm);
    const int tid = threadIdx.x, lane = tid & 31, wid = tid >> 5;
    const int wm = (wid & 3) * 32, wn = (wid >> 2) * 32;
    const int l15 = lane & 15, lhi = lane >> 4;
    const int bm = blockIdx.y * 128, bn = blockIdx.x * 128;
    const int lc = tid & 7, lr = tid >> 3;

    auto load_stage = [&](int st, int kc) {
        const uint32_t sb = sbase + st * STAGE3;
#pragma unroll
        for (int rr = 0; rr < 128; rr += 64) {
            const int r = lr + rr;
            const uint32_t off = (uint32_t)(r * 128) + (uint32_t)((lc ^ (r & 7)) << 4);
            const size_t ga = (size_t)(bm + r) * NM + kc + lc * 8;
            const size_t gb = (size_t)(bn + r) * NM + kc + lc * 8;
            cpa16(sb + 0 * PLANE + off, Ah + ga);
            cpa16(sb + 1 * PLANE + off, Al + ga);
            cpa16(sb + 2 * PLANE + off, Bh + gb);
            cpa16(sb + 3 * PLANE + off, Bl + gb);
        }
    };

    load_stage(0, 0);      cp_commit();
    load_stage(1, BK);     cp_commit();
    load_stage(2, 2 * BK); cp_commit();

    for (int kt = 0; kt < NKT; ++kt) {
        cp_wait2();
        __syncthreads();
        const uint32_t sb = sbase + (kt % 3) * STAGE3;
#pragma unroll
        for (int kh = 0; kh < 4; ++kh) {
            uint32_t ahf[2][4], alf[2][4];
            const int chunkL = (kh << 1) | lhi;
#pragma unroll
            for (int mt = 0; mt < 2; ++mt) {
                const int r = wm + mt * 16 + l15;
                const uint32_t off = (uint32_t)(r * 128) +
                                     (uint32_t)((chunkL ^ (r & 7)) << 4);
                ldsm4(ahf[mt], sb + 0 * PLANE + off);
                ldsm4(alf[mt], sb + 1 * PLANE + off);
            }
#pragma unroll
            for (int g = 0; g < 2; ++g) {
                uint32_t bh4[4], bl4[4];
                const int r = wn + g * 16 + l15;
                const uint32_t off = (uint32_t)(r * 128) +
                                     (uint32_t)((chunkL ^ (r & 7)) << 4);
                ldsm4(bh4, sb + 2 * PLANE + off);
                ldsm4(bl4, sb + 3 * PLANE + off);
#pragma unroll
                for (int mt = 0; mt < 2; ++mt)
#pragma unroll
                    for (int j = 0; j < 2; ++j)
                        mma16816(acc[mt][g * 2 + j], ahf[mt], bh4[j], bh4[j + 2]);
#pragma unroll
                for (int mt = 0; mt < 2; ++mt)
#pragma unroll
                    for (int j = 0; j < 2; ++j)
                        mma16816(acc[mt][g * 2 + j], alf[mt], bh4[j], bh4[j + 2]);
#pragma unroll
                for (int mt = 0; mt < 2; ++mt)
#pragma unroll
                    for (int j = 0; j < 2; ++j)
                        mma16816(acc[mt][g * 2 + j], ahf[mt], bl4[j], bl4[j + 2]);
            }
        }
        __syncthreads();
        if (kt + 3 < NKT) load_stage(kt % 3, (kt + 3) * BK);
        cp_commit();
    }
}

// ----------------------------------------------------------------------------
// 2-term core GEMM: C(128x128) += (Ah + Al) * Bh over K=1536.
// Three smem planes per stage (no Bl): 48 KB stages, 25% less ldsm.
// ----------------------------------------------------------------------------
__device__ __forceinline__ void gemm_main2(
    const __half* __restrict__ Ah, const __half* __restrict__ Al,
    const __half* __restrict__ Bh,
    float (&acc)[2][4][4])
{
    const uint32_t sbase = smem_u32(dsm);
    const int tid = threadIdx.x, lane = tid & 31, wid = tid >> 5;
    const int wm = (wid & 3) * 32, wn = (wid >> 2) * 32;
    const int l15 = lane & 15, lhi = lane >> 4;
    const int bm = blockIdx.y * 128, bn = blockIdx.x * 128;
    const int lc = tid & 7, lr = tid >> 3;

    auto load_stage = [&](int st, int kc) {
        const uint32_t sb = sbase + st * STAGE2;
#pragma unroll
        for (int rr = 0; rr < 128; rr += 64) {
            const int r = lr + rr;
            const uint32_t off = (uint32_t)(r * 128) + (uint32_t)((lc ^ (r & 7)) << 4);
            const size_t ga = (size_t)(bm + r) * NM + kc + lc * 8;
            const size_t gb = (size_t)(bn + r) * NM + kc + lc * 8;
            cpa16(sb + 0 * PLANE + off, Ah + ga);
            cpa16(sb + 1 * PLANE + off, Al + ga);
            cpa16(sb + 2 * PLANE + off, Bh + gb);
        }
    };

    load_stage(0, 0);      cp_commit();
    load_stage(1, BK);     cp_commit();
    load_stage(2, 2 * BK); cp_commit();

    for (int kt = 0; kt < NKT; ++kt) {
        cp_wait2();
        __syncthreads();
        const uint32_t sb = sbase + (kt % 3) * STAGE2;
#pragma unroll
        for (int kh = 0; kh < 4; ++kh) {
            uint32_t ahf[2][4], alf[2][4];
            const int chunkL = (kh << 1) | lhi;
#pragma unroll
            for (int mt = 0; mt < 2; ++mt) {
                const int r = wm + mt * 16 + l15;
                const uint32_t off = (uint32_t)(r * 128) +
                                     (uint32_t)((chunkL ^ (r & 7)) << 4);
                ldsm4(ahf[mt], sb + 0 * PLANE + off);
                ldsm4(alf[mt], sb + 1 * PLANE + off);
            }
#pragma unroll
            for (int g = 0; g < 2; ++g) {
                uint32_t bh4[4];
                const int r = wn + g * 16 + l15;
                const uint32_t off = (uint32_t)(r * 128) +
                                     (uint32_t)((chunkL ^ (r & 7)) << 4);
                ldsm4(bh4, sb + 2 * PLANE + off);
#pragma unroll
                for (int mt = 0; mt < 2; ++mt)
#pragma unroll
                    for (int j = 0; j < 2; ++j)
                        mma16816(acc[mt][g * 2 + j], ahf[mt], bh4[j], bh4[j + 2]);
#pragma unroll
                for (int mt = 0; mt < 2; ++mt)
#pragma unroll
                    for (int j = 0; j < 2; ++j)
                        mma16816(acc[mt][g * 2 + j], alf[mt], bh4[j], bh4[j + 2]);
            }
        }
        __syncthreads();
        if (kt + 3 < NKT) load_stage(kt % 3, (kt + 3) * BK);
        cp_commit();
    }
}

// plain fp32 epilogue -------------------------------------------------------
__device__ __forceinline__ void epi_plain(float (&acc)[2][4][4], float* __restrict__ C)
{
    const int tid = threadIdx.x, lane = tid & 31, wid = tid >> 5;
    const int wm = (wid & 3) * 32, wn = (wid >> 2) * 32;
    const int bm = blockIdx.y * 128, bn = blockIdx.x * 128;
    const int l4 = lane >> 2, l2 = (lane & 3) * 2;
#pragma unroll
    for (int mt = 0; mt < 2; ++mt)
#pragma unroll
        for (int h = 0; h < 2; ++h) {
            const int row = bm + wm + mt * 16 + l4 + h * 8;
#pragma unroll
            for (int nt = 0; nt < 4; ++nt) {
                const int col = bn + wn + nt * 8 + l2;
                *(float2*)(C + (size_t)row * NM + col) =
                    make_float2(acc[mt][nt][2 * h], acc[mt][nt][2 * h + 1]);
            }
        }
}

// ----------------------------------------------------------------------------
// Kernels
// ----------------------------------------------------------------------------

// Chebyshev step (3-term): T_step = 2 * L @ B - D; writes fp32 + fp16 hi/lo.
__global__ void __launch_bounds__(512)
k_gemm_cheb(const float* __restrict__ L32, int side, int step)
{
    const __half* Ah = side ? g_Lch : g_Lrh;
    const __half* Al = side ? g_Lcl : g_Lrl;
    const __half* Bh = (step == 0) ? Ah : (side ? g_Tch[step - 1] : g_Trh[step - 1]);
    const __half* Bl = (step == 0) ? Al : (side ? g_Tcl[step - 1] : g_Trl[step - 1]);
    const float* D = (step == 0) ? nullptr
                   : (step == 1) ? L32
                   : (side ? g_Tc32[0] : g_Tr32[0]);
    float* C = side ? g_Tc32[step] : g_Tr32[step];
    __half* Ho = side ? g_Tch[step] : g_Trh[step];
    __half* Lo = side ? g_Tcl[step] : g_Trl[step];

    float acc[2][4][4] = {};
    gemm_main3(Ah, Al, Bh, Bl, acc);

    const int tid = threadIdx.x, lane = tid & 31, wid = tid >> 5;
    const int wm = (wid & 3) * 32, wn = (wid >> 2) * 32;
    const int bm = blockIdx.y * 128, bn = blockIdx.x * 128;
    const int l4 = lane >> 2, l2 = (lane & 3) * 2;
#pragma unroll
    for (int mt = 0; mt < 2; ++mt)
#pragma unroll
        for (int h = 0; h < 2; ++h) {
            const int row = bm + wm + mt * 16 + l4 + h * 8;
#pragma unroll
            for (int nt = 0; nt < 4; ++nt) {
                const int col = bn + wn + nt * 8 + l2;
                const size_t off = (size_t)row * NM + col;
                float2 d;
                if (D) d = *(const float2*)(D + off);
                else   d = make_float2(row == col ? 1.f : 0.f,
                                       row == col + 1 ? 1.f : 0.f);
                const float vx = 2.f * acc[mt][nt][2 * h]     - d.x;
                const float vy = 2.f * acc[mt][nt][2 * h + 1] - d.y;
                *(float2*)(C + off) = make_float2(vx, vy);
                const __half hx = __float2half_rn(vx);
                const __half hy = __float2half_rn(vy);
                __half2 q;
                q.x = hx; q.y = hy;
                *(__half2*)(Ho + off) = q;
                q.x = __float2half_rn(vx - __half2float(hx));
                q.y = __float2half_rn(vy - __half2float(hy));
                *(__half2*)(Lo + off) = q;
            }
        }
}

// W_j = X @ Tc_j (3-term; feeds Z): j-1 = blockIdx.z
__global__ void __launch_bounds__(512)
k_gemm_w()
{
    const int z = blockIdx.z;
    const __half* Bh = (z == 0) ? g_Lch : g_Tch[z - 1];
    const __half* Bl = (z == 0) ? g_Lcl : g_Tcl[z - 1];
    float acc[2][4][4] = {};
    gemm_main3(g_Xh, g_Xl, Bh, Bl, acc);
    epi_plain(acc, g_W32[z]);
}

// Y_i = Tr_i @ X (2-term; terminal): i-1 = blockIdx.z; B = X^T hi.
__global__ void __launch_bounds__(512)
k_gemm_y()
{
    const int z = blockIdx.z;
    const __half* Ah = (z == 0) ? g_Lrh : g_Trh[z - 1];
    const __half* Al = (z == 0) ? g_Lrl : g_Trl[z - 1];
    float acc[2][4][4] = {};
    gemm_main2(Ah, Al, g_XTh, acc);
    epi_plain(acc, g_Y32[z]);
}

// Z_ij = Tr_i @ W_j (2-term; terminal): z = (i-1)*4 + (j-1); B = W_j^T hi.
__global__ void __launch_bounds__(512)
k_gemm_z()
{
    const int z = blockIdx.z;
    const int i = z >> 2, j = z & 3;
    const __half* Ah = (i == 0) ? g_Lrh : g_Trh[i - 1];
    const __half* Al = (i == 0) ? g_Lrl : g_Trl[i - 1];
    float acc[2][4][4] = {};
    gemm_main2(Ah, Al, g_WTh[j], acc);
    epi_plain(acc, g_Z32[z]);
}

// ----------------------------------------------------------------------------
// fp32 -> fp16 hi/lo conversion of inputs (z: 0=X, 1=Lr, 2=Lc)
__global__ void __launch_bounds__(256)
k_cvt(const float* __restrict__ x, const float* __restrict__ Lr,
      const float* __restrict__ Lc)
{
    const int zz = blockIdx.z;
    const float* s = (zz == 0) ? x : (zz == 1) ? Lr : Lc;
    __half* H = (zz == 0) ? g_Xh : (zz == 1) ? g_Lrh : g_Lch;
    __half* L = (zz == 0) ? g_Xl : (zz == 1) ? g_Lrl : g_Lcl;
    const int i = (blockIdx.x * 256 + threadIdx.x) * 4;
    float4 v = *(const float4*)(s + i);
    __half h0 = __float2half_rn(v.x), h1 = __float2half_rn(v.y);
    __half h2 = __float2half_rn(v.z), h3 = __float2half_rn(v.w);
    __half2 p;
    p.x = h0; p.y = h1; *(__half2*)(H + i)     = p;
    p.x = h2; p.y = h3; *(__half2*)(H + i + 2) = p;
    p.x = __float2half_rn(v.x - __half2float(h0));
    p.y = __float2half_rn(v.y - __half2float(h1));
    *(__half2*)(L + i) = p;
    p.x = __float2half_rn(v.z - __half2float(h2));
    p.y = __float2half_rn(v.w - __half2float(h3));
    *(__half2*)(L + i + 2) = p;
}

// X^T hi (2-term Y only needs hi)
__global__ void __launch_bounds__(256)
k_cvtT(const float* __restrict__ X)
{
    __shared__ float t[32][33];
    const int tx = threadIdx.x, ty = threadIdx.y;
    const int n0 = blockIdx.x * 32, m0 = blockIdx.y * 32;
#pragma unroll
    for (int i = 0; i < 4; ++i)
        t[ty + 8 * i][tx] = X[(size_t)(m0 + ty + 8 * i) * NM + n0 + tx];
    __syncthreads();
#pragma unroll
    for (int i = 0; i < 4; ++i) {
        const int nl = ty + 8 * i;
        const float v = t[tx][nl];                    // X[m0+tx][n0+nl]
        g_XTh[(size_t)(n0 + nl) * NM + m0 + tx] = __float2half_rn(v);
    }
}

// W^T hi (z = j-1) -- 2-term Z only needs hi
__global__ void __launch_bounds__(256)
k_trW()
{
    const int z = blockIdx.z;
    const float* S = g_W32[z];
    __half* TH = g_WTh[z];
    __shared__ float t[32][33];
    const int tx = threadIdx.x, ty = threadIdx.y;
    const int n0 = blockIdx.x * 32, m0 = blockIdx.y * 32;
#pragma unroll
    for (int i = 0; i < 4; ++i)
        t[ty + 8 * i][tx] = S[(size_t)(m0 + ty + 8 * i) * NM + n0 + tx];
    __syncthreads();
#pragma unroll
    for (int i = 0; i < 4; ++i) {
        const int nl = ty + 8 * i;
        TH[(size_t)(n0 + nl) * NM + m0 + tx] = __float2half_rn(t[tx][nl]);
    }
}

// ----------------------------------------------------------------------------
// Final mix: out[o,m,n] = bias[o] + sum_t theta[t,o] * plane_t[m,n]
__global__ void __launch_bounds__(256)
k_mix(const float* __restrict__ x, const float* __restrict__ theta,
      const float* __restrict__ bias, float* __restrict__ out)
{
    __shared__ float sh_th[25 * OUTC];
    __shared__ float sh_b[OUTC];
    const int tid = threadIdx.x;
    for (int t = tid; t < 25 * OUTC; t += 256) sh_th[t] = theta[t];
    if (tid < OUTC) sh_b[tid] = bias[tid];
    __syncthreads();

    const int off = (blockIdx.x * 256 + tid) * 2;

    float2 v[25];
    v[0] = *(const float2*)(x + off);
#pragma unroll
    for (int j = 1; j <= 4; ++j) v[j] = *(const float2*)(g_W32[j - 1] + off);
#pragma unroll
    for (int i = 1; i <= 4; ++i) v[i * 5] = *(const float2*)(g_Y32[i - 1] + off);
#pragma unroll
    for (int i = 1; i <= 4; ++i)
#pragma unroll
        for (int j = 1; j <= 4; ++j)
            v[i * 5 + j] = *(const float2*)(g_Z32[(i - 1) * 4 + (j - 1)] + off);

#pragma unroll
    for (int o = 0; o < OUTC; ++o) {
        float sx = sh_b[o], sy = sh_b[o];
#pragma unroll
        for (int t = 0; t < 25; ++t) {
            const float w = sh_th[t * OUTC + o];
            sx += w * v[t].x;
            sy += w * v[t].y;
        }
        *(float2*)(out + (size_t)o * N2 + off) = make_float2(sx, sy);
    }
}

// ----------------------------------------------------------------------------
extern "C" void kernel_launch(void* const* d_in, const int* in_sizes, int n_in,
                              void* d_out, int out_size)
{
    const float* x     = (const float*)d_in[0];
    const float* Lr    = (const float*)d_in[1];
    const float* Lc    = (const float*)d_in[2];
    const float* theta = (const float*)d_in[3];
    const float* bias  = (const float*)d_in[4];
    float* out = (float*)d_out;

    cudaFuncSetAttribute(k_gemm_cheb, cudaFuncAttributeMaxDynamicSharedMemorySize, SMEM_DYN3);
    cudaFuncSetAttribute(k_gemm_w,    cudaFuncAttributeMaxDynamicSharedMemorySize, SMEM_DYN3);
    cudaFuncSetAttribute(k_gemm_y,    cudaFuncAttributeMaxDynamicSharedMemorySize, SMEM_DYN2);
    cudaFuncSetAttribute(k_gemm_z,    cudaFuncAttributeMaxDynamicSharedMemorySize, SMEM_DYN2);

    const dim3 blk(512);
    const dim3 g2(NM / 128, NM / 128, 1);        // (12,12)
    const dim3 blkT(32, 8);
    const dim3 gT(NM / 32, NM / 32, 1);

    // input conversions
    k_cvt<<<dim3(N2 / 1024, 1, 3), 256>>>(x, Lr, Lc);
    k_cvtT<<<gT, blkT>>>(x);

    // Chebyshev bases (sequential per side, 3-term)
    for (int step = 0; step < 3; ++step)
        k_gemm_cheb<<<g2, blk, SMEM_DYN3>>>(Lr, 0, step);
    for (int step = 0; step < 3; ++step)
        k_gemm_cheb<<<g2, blk, SMEM_DYN3>>>(Lc, 1, step);

    // W_j = X @ Tc_j (3-term; feeds Z)
    k_gemm_w<<<dim3(12, 12, 4), blk, SMEM_DYN3>>>();
    // W^T hi for the Z-stage B operands
    k_trW<<<dim3(NM / 32, NM / 32, 4), blkT>>>();
    // Y_i = Tr_i @ X (2-term)
    k_gemm_y<<<dim3(12, 12, 4), blk, SMEM_DYN2>>>();
    // Z_ij = Tr_i @ W_j (2-term)
    k_gemm_z<<<dim3(12, 12, 16), blk, SMEM_DYN2>>>();

    // final 25-term mix
    k_mix<<<N2 / 512, 256>>>(x, theta, bias, out);
}

// round 11
// speedup vs baseline: 3.8046x; 1.4273x over previous
#include <cuda_runtime.h>
#include <cuda_fp16.h>
#include <cstdint>

// ============================================================================
// BilinearChebConv via mma.sync (fp16 split GEMMs, fp32 accumulate)
// out[o] = sum_{i,j} theta[i,j,o] * (Tr_i @ X @ Tc_j) + bias[o]
// M = N = 1536, orders 4/4, OUT = 32.
// R11: time is MMA-count-bound (tensor dispatch ceiling). Units 70 -> 46:
//   - Y, Z -> 1-term (Ah*Bh): terminal error ~2.3e-4 total, no amplification
//   - W -> 2-term (drop Xh*Tcl): W feeds Z via fp16-rounded WTh anyway
//   - Chebyshev chain stays 3-term (errors amplify ~2x/step in recursion)
// 1-term stages use 2 smem planes (32KB/stage).
// ============================================================================

constexpr int NM   = 1536;
constexpr int N2   = NM * NM;
constexpr int OUTC = 32;

constexpr int BK     = 64;                  // k per stage (64 fp16 = 128B row)
constexpr int NKT    = NM / BK;             // 24
constexpr int PLANE  = 128 * 128;           // bytes per operand plane per stage
constexpr int STAGE3 = 4 * PLANE;           // Ah|Al|Bh|Bl = 64 KB (3-term)
constexpr int STAGE2 = 3 * PLANE;           // Ah|Al|Bh    = 48 KB (2-term)
constexpr int STAGE1 = 2 * PLANE;           // Ah|Bh       = 32 KB (1-term)
constexpr unsigned SMEM_DYN3 = 3 * STAGE3;  // 192 KB
constexpr unsigned SMEM_DYN2 = 3 * STAGE2;  // 144 KB
constexpr unsigned SMEM_DYN1 = 3 * STAGE1;  //  96 KB

// ----------------------------------------------------------------------------
// Scratch (no cudaMalloc allowed -> __device__ globals)
__device__ float g_Tr32[3][N2];
__device__ float g_Tc32[3][N2];
__device__ float g_W32[4][N2];          // W_j = X @ Tc_j      (= Z_{0,j})
__device__ float g_Y32[4][N2];          // Y_i = Tr_i @ X      (= Z_{i,0})
__device__ float g_Z32[16][N2];         // Z_ij = Tr_i @ W_j,  i,j = 1..4
// fp16 hi/lo operand planes (all B operands stored as N x K)
__device__ __half g_Xh[N2],  g_Xl[N2];      // X   (A operand, row-major)
__device__ __half g_XTh[N2];                // X^T hi (B for Y-stage)
__device__ __half g_Lrh[N2], g_Lrl[N2];
__device__ __half g_Lch[N2], g_Lcl[N2];
__device__ __half g_Trh[3][N2], g_Trl[3][N2];   // symmetric -> B directly
__device__ __half g_Tch[3][N2], g_Tcl[3][N2];
__device__ __half g_WTh[4][N2];                 // W_j^T hi (B for Z)

// ----------------------------------------------------------------------------
// PTX helpers (all baseline sm_80+ instructions)
// ----------------------------------------------------------------------------
__device__ __forceinline__ uint32_t smem_u32(const void* p) {
    uint32_t a;
    asm("{ .reg .u64 t; cvta.to.shared.u64 t, %1; cvt.u32.u64 %0, t; }"
        : "=r"(a) : "l"(p));
    return a;
}
__device__ __forceinline__ void cpa16(uint32_t s, const void* g) {
    asm volatile("cp.async.cg.shared.global [%0], [%1], 16;\n" :: "r"(s), "l"(g));
}
__device__ __forceinline__ void cp_commit() {
    asm volatile("cp.async.commit_group;\n" ::: "memory");
}
__device__ __forceinline__ void cp_wait2() {
    asm volatile("cp.async.wait_group 2;\n" ::: "memory");
}
__device__ __forceinline__ void ldsm4(uint32_t* r, uint32_t a) {
    asm volatile("ldmatrix.sync.aligned.m8n8.x4.shared.b16 {%0,%1,%2,%3}, [%4];"
                 : "=r"(r[0]), "=r"(r[1]), "=r"(r[2]), "=r"(r[3]) : "r"(a));
}
__device__ __forceinline__ void mma16816(float* c, const uint32_t* a,
                                         uint32_t b0, uint32_t b1) {
    asm volatile("mma.sync.aligned.m16n8k16.row.col.f32.f16.f16.f32 "
                 "{%0,%1,%2,%3}, {%4,%5,%6,%7}, {%8,%9}, {%0,%1,%2,%3};"
                 : "+f"(c[0]), "+f"(c[1]), "+f"(c[2]), "+f"(c[3])
                 : "r"(a[0]), "r"(a[1]), "r"(a[2]), "r"(a[3]), "r"(b0), "r"(b1));
}

extern __shared__ char dsm[];

// ----------------------------------------------------------------------------
// 3-term core GEMM: C(128x128) += (AhBh + AlBh + AhBl) over K=1536.
// Block = 512 threads, 16 warps of 32x32. acc[2][4][4] per thread.
// ----------------------------------------------------------------------------
__device__ __forceinline__ void gemm_main3(
    const __half* __restrict__ Ah, const __half* __restrict__ Al,
    const __half* __restrict__ Bh, const __half* __restrict__ Bl,
    float (&acc)[2][4][4])
{
    const uint32_t sbase = smem_u32(dsm);
    const int tid = threadIdx.x, lane = tid & 31, wid = tid >> 5;
    const int wm = (wid & 3) * 32, wn = (wid >> 2) * 32;
    const int l15 = lane & 15, lhi = lane >> 4;
    const int bm = blockIdx.y * 128, bn = blockIdx.x * 128;
    const int lc = tid & 7, lr = tid >> 3;

    auto load_stage = [&](int st, int kc) {
        const uint32_t sb = sbase + st * STAGE3;
#pragma unroll
        for (int rr = 0; rr < 128; rr += 64) {
            const int r = lr + rr;
            const uint32_t off = (uint32_t)(r * 128) + (uint32_t)((lc ^ (r & 7)) << 4);
            const size_t ga = (size_t)(bm + r) * NM + kc + lc * 8;
            const size_t gb = (size_t)(bn + r) * NM + kc + lc * 8;
            cpa16(sb + 0 * PLANE + off, Ah + ga);
            cpa16(sb + 1 * PLANE + off, Al + ga);
            cpa16(sb + 2 * PLANE + off, Bh + gb);
            cpa16(sb + 3 * PLANE + off, Bl + gb);
        }
    };

    load_stage(0, 0);      cp_commit();
    load_stage(1, BK);     cp_commit();
    load_stage(2, 2 * BK); cp_commit();

    for (int kt = 0; kt < NKT; ++kt) {
        cp_wait2();
        __syncthreads();
        const uint32_t sb = sbase + (kt % 3) * STAGE3;
#pragma unroll
        for (int kh = 0; kh < 4; ++kh) {
            uint32_t ahf[2][4], alf[2][4];
            const int chunkL = (kh << 1) | lhi;
#pragma unroll
            for (int mt = 0; mt < 2; ++mt) {
                const int r = wm + mt * 16 + l15;
                const uint32_t off = (uint32_t)(r * 128) +
                                     (uint32_t)((chunkL ^ (r & 7)) << 4);
                ldsm4(ahf[mt], sb + 0 * PLANE + off);
                ldsm4(alf[mt], sb + 1 * PLANE + off);
            }
#pragma unroll
            for (int g = 0; g < 2; ++g) {
                uint32_t bh4[4], bl4[4];
                const int r = wn + g * 16 + l15;
                const uint32_t off = (uint32_t)(r * 128) +
                                     (uint32_t)((chunkL ^ (r & 7)) << 4);
                ldsm4(bh4, sb + 2 * PLANE + off);
                ldsm4(bl4, sb + 3 * PLANE + off);
#pragma unroll
                for (int mt = 0; mt < 2; ++mt)
#pragma unroll
                    for (int j = 0; j < 2; ++j)
                        mma16816(acc[mt][g * 2 + j], ahf[mt], bh4[j], bh4[j + 2]);
#pragma unroll
                for (int mt = 0; mt < 2; ++mt)
#pragma unroll
                    for (int j = 0; j < 2; ++j)
                        mma16816(acc[mt][g * 2 + j], alf[mt], bh4[j], bh4[j + 2]);
#pragma unroll
                for (int mt = 0; mt < 2; ++mt)
#pragma unroll
                    for (int j = 0; j < 2; ++j)
                        mma16816(acc[mt][g * 2 + j], ahf[mt], bl4[j], bl4[j + 2]);
            }
        }
        __syncthreads();
        if (kt + 3 < NKT) load_stage(kt % 3, (kt + 3) * BK);
        cp_commit();
    }
}

// ----------------------------------------------------------------------------
// 2-term core GEMM: C(128x128) += (Ah + Al) * Bh over K=1536.
// ----------------------------------------------------------------------------
__device__ __forceinline__ void gemm_main2(
    const __half* __restrict__ Ah, const __half* __restrict__ Al,
    const __half* __restrict__ Bh,
    float (&acc)[2][4][4])
{
    const uint32_t sbase = smem_u32(dsm);
    const int tid = threadIdx.x, lane = tid & 31, wid = tid >> 5;
    const int wm = (wid & 3) * 32, wn = (wid >> 2) * 32;
    const int l15 = lane & 15, lhi = lane >> 4;
    const int bm = blockIdx.y * 128, bn = blockIdx.x * 128;
    const int lc = tid & 7, lr = tid >> 3;

    auto load_stage = [&](int st, int kc) {
        const uint32_t sb = sbase + st * STAGE2;
#pragma unroll
        for (int rr = 0; rr < 128; rr += 64) {
            const int r = lr + rr;
            const uint32_t off = (uint32_t)(r * 128) + (uint32_t)((lc ^ (r & 7)) << 4);
            const size_t ga = (size_t)(bm + r) * NM + kc + lc * 8;
            const size_t gb = (size_t)(bn + r) * NM + kc + lc * 8;
            cpa16(sb + 0 * PLANE + off, Ah + ga);
            cpa16(sb + 1 * PLANE + off, Al + ga);
            cpa16(sb + 2 * PLANE + off, Bh + gb);
        }
    };

    load_stage(0, 0);      cp_commit();
    load_stage(1, BK);     cp_commit();
    load_stage(2, 2 * BK); cp_commit();

    for (int kt = 0; kt < NKT; ++kt) {
        cp_wait2();
        __syncthreads();
        const uint32_t sb = sbase + (kt % 3) * STAGE2;
#pragma unroll
        for (int kh = 0; kh < 4; ++kh) {
            uint32_t ahf[2][4], alf[2][4];
            const int chunkL = (kh << 1) | lhi;
#pragma unroll
            for (int mt = 0; mt < 2; ++mt) {
                const int r = wm + mt * 16 + l15;
                const uint32_t off = (uint32_t)(r * 128) +
                                     (uint32_t)((chunkL ^ (r & 7)) << 4);
                ldsm4(ahf[mt], sb + 0 * PLANE + off);
                ldsm4(alf[mt], sb + 1 * PLANE + off);
            }
#pragma unroll
            for (int g = 0; g < 2; ++g) {
                uint32_t bh4[4];
                const int r = wn + g * 16 + l15;
                const uint32_t off = (uint32_t)(r * 128) +
                                     (uint32_t)((chunkL ^ (r & 7)) << 4);
                ldsm4(bh4, sb + 2 * PLANE + off);
#pragma unroll
                for (int mt = 0; mt < 2; ++mt)
#pragma unroll
                    for (int j = 0; j < 2; ++j)
                        mma16816(acc[mt][g * 2 + j], ahf[mt], bh4[j], bh4[j + 2]);
#pragma unroll
                for (int mt = 0; mt < 2; ++mt)
#pragma unroll
                    for (int j = 0; j < 2; ++j)
                        mma16816(acc[mt][g * 2 + j], alf[mt], bh4[j], bh4[j + 2]);
            }
        }
        __syncthreads();
        if (kt + 3 < NKT) load_stage(kt % 3, (kt + 3) * BK);
        cp_commit();
    }
}

// ----------------------------------------------------------------------------
// 1-term core GEMM: C(128x128) += Ah * Bh over K=1536. Two smem planes.
// ----------------------------------------------------------------------------
__device__ __forceinline__ void gemm_main1(
    const __half* __restrict__ Ah, const __half* __restrict__ Bh,
    float (&acc)[2][4][4])
{
    const uint32_t sbase = smem_u32(dsm);
    const int tid = threadIdx.x, lane = tid & 31, wid = tid >> 5;
    const int wm = (wid & 3) * 32, wn = (wid >> 2) * 32;
    const int l15 = lane & 15, lhi = lane >> 4;
    const int bm = blockIdx.y * 128, bn = blockIdx.x * 128;
    const int lc = tid & 7, lr = tid >> 3;

    auto load_stage = [&](int st, int kc) {
        const uint32_t sb = sbase + st * STAGE1;
#pragma unroll
        for (int rr = 0; rr < 128; rr += 64) {
            const int r = lr + rr;
            const uint32_t off = (uint32_t)(r * 128) + (uint32_t)((lc ^ (r & 7)) << 4);
            const size_t ga = (size_t)(bm + r) * NM + kc + lc * 8;
            const size_t gb = (size_t)(bn + r) * NM + kc + lc * 8;
            cpa16(sb + 0 * PLANE + off, Ah + ga);
            cpa16(sb + 1 * PLANE + off, Bh + gb);
        }
    };

    load_stage(0, 0);      cp_commit();
    load_stage(1, BK);     cp_commit();
    load_stage(2, 2 * BK); cp_commit();

    for (int kt = 0; kt < NKT; ++kt) {
        cp_wait2();
        __syncthreads();
        const uint32_t sb = sbase + (kt % 3) * STAGE1;
#pragma unroll
        for (int kh = 0; kh < 4; ++kh) {
            uint32_t ahf[2][4];
            const int chunkL = (kh << 1) | lhi;
#pragma unroll
            for (int mt = 0; mt < 2; ++mt) {
                const int r = wm + mt * 16 + l15;
                const uint32_t off = (uint32_t)(r * 128) +
                                     (uint32_t)((chunkL ^ (r & 7)) << 4);
                ldsm4(ahf[mt], sb + 0 * PLANE + off);
            }
#pragma unroll
            for (int g = 0; g < 2; ++g) {
                uint32_t bh4[4];
                const int r = wn + g * 16 + l15;
                const uint32_t off = (uint32_t)(r * 128) +
                                     (uint32_t)((chunkL ^ (r & 7)) << 4);
                ldsm4(bh4, sb + 1 * PLANE + off);
#pragma unroll
                for (int mt = 0; mt < 2; ++mt)
#pragma unroll
                    for (int j = 0; j < 2; ++j)
                        mma16816(acc[mt][g * 2 + j], ahf[mt], bh4[j], bh4[j + 2]);
            }
        }
        __syncthreads();
        if (kt + 3 < NKT) load_stage(kt % 3, (kt + 3) * BK);
        cp_commit();
    }
}

// plain fp32 epilogue -------------------------------------------------------
__device__ __forceinline__ void epi_plain(float (&acc)[2][4][4], float* __restrict__ C)
{
    const int tid = threadIdx.x, lane = tid & 31, wid = tid >> 5;
    const int wm = (wid & 3) * 32, wn = (wid >> 2) * 32;
    const int bm = blockIdx.y * 128, bn = blockIdx.x * 128;
    const int l4 = lane >> 2, l2 = (lane & 3) * 2;
#pragma unroll
    for (int mt = 0; mt < 2; ++mt)
#pragma unroll
        for (int h = 0; h < 2; ++h) {
            const int row = bm + wm + mt * 16 + l4 + h * 8;
#pragma unroll
            for (int nt = 0; nt < 4; ++nt) {
                const int col = bn + wn + nt * 8 + l2;
                *(float2*)(C + (size_t)row * NM + col) =
                    make_float2(acc[mt][nt][2 * h], acc[mt][nt][2 * h + 1]);
            }
        }
}

// ----------------------------------------------------------------------------
// Kernels
// ----------------------------------------------------------------------------

// Chebyshev step (3-term): T_step = 2 * L @ B - D; writes fp32 + fp16 hi/lo.
__global__ void __launch_bounds__(512)
k_gemm_cheb(const float* __restrict__ L32, int side, int step)
{
    const __half* Ah = side ? g_Lch : g_Lrh;
    const __half* Al = side ? g_Lcl : g_Lrl;
    const __half* Bh = (step == 0) ? Ah : (side ? g_Tch[step - 1] : g_Trh[step - 1]);
    const __half* Bl = (step == 0) ? Al : (side ? g_Tcl[step - 1] : g_Trl[step - 1]);
    const float* D = (step == 0) ? nullptr
                   : (step == 1) ? L32
                   : (side ? g_Tc32[0] : g_Tr32[0]);
    float* C = side ? g_Tc32[step] : g_Tr32[step];
    __half* Ho = side ? g_Tch[step] : g_Trh[step];
    __half* Lo = side ? g_Tcl[step] : g_Trl[step];

    float acc[2][4][4] = {};
    gemm_main3(Ah, Al, Bh, Bl, acc);

    const int tid = threadIdx.x, lane = tid & 31, wid = tid >> 5;
    const int wm = (wid & 3) * 32, wn = (wid >> 2) * 32;
    const int bm = blockIdx.y * 128, bn = blockIdx.x * 128;
    const int l4 = lane >> 2, l2 = (lane & 3) * 2;
#pragma unroll
    for (int mt = 0; mt < 2; ++mt)
#pragma unroll
        for (int h = 0; h < 2; ++h) {
            const int row = bm + wm + mt * 16 + l4 + h * 8;
#pragma unroll
            for (int nt = 0; nt < 4; ++nt) {
                const int col = bn + wn + nt * 8 + l2;
                const size_t off = (size_t)row * NM + col;
                float2 d;
                if (D) d = *(const float2*)(D + off);
                else   d = make_float2(row == col ? 1.f : 0.f,
                                       row == col + 1 ? 1.f : 0.f);
                const float vx = 2.f * acc[mt][nt][2 * h]     - d.x;
                const float vy = 2.f * acc[mt][nt][2 * h + 1] - d.y;
                *(float2*)(C + off) = make_float2(vx, vy);
                const __half hx = __float2half_rn(vx);
                const __half hy = __float2half_rn(vy);
                __half2 q;
                q.x = hx; q.y = hy;
                *(__half2*)(Ho + off) = q;
                q.x = __float2half_rn(vx - __half2float(hx));
                q.y = __float2half_rn(vy - __half2float(hy));
                *(__half2*)(Lo + off) = q;
            }
        }
}

// W_j = X @ Tc_j (2-term: (Xh+Xl)*Tch; feeds mix + fp16-rounded WTh): j-1 = z
__global__ void __launch_bounds__(512)
k_gemm_w()
{
    const int z = blockIdx.z;
    const __half* Bh = (z == 0) ? g_Lch : g_Tch[z - 1];
    float acc[2][4][4] = {};
    gemm_main2(g_Xh, g_Xl, Bh, acc);
    epi_plain(acc, g_W32[z]);
}

// Y_i = Tr_i @ X (1-term; terminal): i-1 = blockIdx.z; A = Tr hi, B = X^T hi.
__global__ void __launch_bounds__(512)
k_gemm_y()
{
    const int z = blockIdx.z;
    const __half* Ah = (z == 0) ? g_Lrh : g_Trh[z - 1];
    float acc[2][4][4] = {};
    gemm_main1(Ah, g_XTh, acc);
    epi_plain(acc, g_Y32[z]);
}

// Z_ij = Tr_i @ W_j (1-term; terminal): z = (i-1)*4 + (j-1).
__global__ void __launch_bounds__(512)
k_gemm_z()
{
    const int z = blockIdx.z;
    const int i = z >> 2, j = z & 3;
    const __half* Ah = (i == 0) ? g_Lrh : g_Trh[i - 1];
    float acc[2][4][4] = {};
    gemm_main1(Ah, g_WTh[j], acc);
    epi_plain(acc, g_Z32[z]);
}

// ----------------------------------------------------------------------------
// fp32 -> fp16 hi/lo conversion of inputs (z: 0=X, 1=Lr, 2=Lc)
__global__ void __launch_bounds__(256)
k_cvt(const float* __restrict__ x, const float* __restrict__ Lr,
      const float* __restrict__ Lc)
{
    const int zz = blockIdx.z;
    const float* s = (zz == 0) ? x : (zz == 1) ? Lr : Lc;
    __half* H = (zz == 0) ? g_Xh : (zz == 1) ? g_Lrh : g_Lch;
    __half* L = (zz == 0) ? g_Xl : (zz == 1) ? g_Lrl : g_Lcl;
    const int i = (blockIdx.x * 256 + threadIdx.x) * 4;
    float4 v = *(const float4*)(s + i);
    __half h0 = __float2half_rn(v.x), h1 = __float2half_rn(v.y);
    __half h2 = __float2half_rn(v.z), h3 = __float2half_rn(v.w);
    __half2 p;
    p.x = h0; p.y = h1; *(__half2*)(H + i)     = p;
    p.x = h2; p.y = h3; *(__half2*)(H + i + 2) = p;
    p.x = __float2half_rn(v.x - __half2float(h0));
    p.y = __float2half_rn(v.y - __half2float(h1));
    *(__half2*)(L + i) = p;
    p.x = __float2half_rn(v.z - __half2float(h2));
    p.y = __float2half_rn(v.w - __half2float(h3));
    *(__half2*)(L + i + 2) = p;
}

// X^T hi (1-term Y only needs hi)
__global__ void __launch_bounds__(256)
k_cvtT(const float* __restrict__ X)
{
    __shared__ float t[32][33];
    const int tx = threadIdx.x, ty = threadIdx.y;
    const int n0 = blockIdx.x * 32, m0 = blockIdx.y * 32;
#pragma unroll
    for (int i = 0; i < 4; ++i)
        t[ty + 8 * i][tx] = X[(size_t)(m0 + ty + 8 * i) * NM + n0 + tx];
    __syncthreads();
#pragma unroll
    for (int i = 0; i < 4; ++i) {
        const int nl = ty + 8 * i;
        g_XTh[(size_t)(n0 + nl) * NM + m0 + tx] = __float2half_rn(t[tx][nl]);
    }
}

// W^T hi (z = j-1) -- 1-term Z only needs hi
__global__ void __launch_bounds__(256)
k_trW()
{
    const int z = blockIdx.z;
    const float* S = g_W32[z];
    __half* TH = g_WTh[z];
    __shared__ float t[32][33];
    const int tx = threadIdx.x, ty = threadIdx.y;
    const int n0 = blockIdx.x * 32, m0 = blockIdx.y * 32;
#pragma unroll
    for (int i = 0; i < 4; ++i)
        t[ty + 8 * i][tx] = S[(size_t)(m0 + ty + 8 * i) * NM + n0 + tx];
    __syncthreads();
#pragma unroll
    for (int i = 0; i < 4; ++i) {
        const int nl = ty + 8 * i;
        TH[(size_t)(n0 + nl) * NM + m0 + tx] = __float2half_rn(t[tx][nl]);
    }
}

// ----------------------------------------------------------------------------
// Final mix: out[o,m,n] = bias[o] + sum_t theta[t,o] * plane_t[m,n]
__global__ void __launch_bounds__(256)
k_mix(const float* __restrict__ x, const float* __restrict__ theta,
      const float* __restrict__ bias, float* __restrict__ out)
{
    __shared__ float sh_th[25 * OUTC];
    __shared__ float sh_b[OUTC];
    const int tid = threadIdx.x;
    for (int t = tid; t < 25 * OUTC; t += 256) sh_th[t] = theta[t];
    if (tid < OUTC) sh_b[tid] = bias[tid];
    __syncthreads();

    const int off = (blockIdx.x * 256 + tid) * 2;

    float2 v[25];
    v[0] = *(const float2*)(x + off);
#pragma unroll
    for (int j = 1; j <= 4; ++j) v[j] = *(const float2*)(g_W32[j - 1] + off);
#pragma unroll
    for (int i = 1; i <= 4; ++i) v[i * 5] = *(const float2*)(g_Y32[i - 1] + off);
#pragma unroll
    for (int i = 1; i <= 4; ++i)
#pragma unroll
        for (int j = 1; j <= 4; ++j)
            v[i * 5 + j] = *(const float2*)(g_Z32[(i - 1) * 4 + (j - 1)] + off);

#pragma unroll
    for (int o = 0; o < OUTC; ++o) {
        float sx = sh_b[o], sy = sh_b[o];
#pragma unroll
        for (int t = 0; t < 25; ++t) {
            const float w = sh_th[t * OUTC + o];
            sx += w * v[t].x;
            sy += w * v[t].y;
        }
        *(float2*)(out + (size_t)o * N2 + off) = make_float2(sx, sy);
    }
}

// ----------------------------------------------------------------------------
extern "C" void kernel_launch(void* const* d_in, const int* in_sizes, int n_in,
                              void* d_out, int out_size)
{
    const float* x     = (const float*)d_in[0];
    const float* Lr    = (const float*)d_in[1];
    const float* Lc    = (const float*)d_in[2];
    const float* theta = (const float*)d_in[3];
    const float* bias  = (const float*)d_in[4];
    float* out = (float*)d_out;

    cudaFuncSetAttribute(k_gemm_cheb, cudaFuncAttributeMaxDynamicSharedMemorySize, SMEM_DYN3);
    cudaFuncSetAttribute(k_gemm_w,    cudaFuncAttributeMaxDynamicSharedMemorySize, SMEM_DYN2);
    cudaFuncSetAttribute(k_gemm_y,    cudaFuncAttributeMaxDynamicSharedMemorySize, SMEM_DYN1);
    cudaFuncSetAttribute(k_gemm_z,    cudaFuncAttributeMaxDynamicSharedMemorySize, SMEM_DYN1);

    const dim3 blk(512);
    const dim3 g2(NM / 128, NM / 128, 1);        // (12,12)
    const dim3 blkT(32, 8);
    const dim3 gT(NM / 32, NM / 32, 1);

    // input conversions
    k_cvt<<<dim3(N2 / 1024, 1, 3), 256>>>(x, Lr, Lc);
    k_cvtT<<<gT, blkT>>>(x);

    // Chebyshev bases (sequential per side, 3-term)
    for (int step = 0; step < 3; ++step)
        k_gemm_cheb<<<g2, blk, SMEM_DYN3>>>(Lr, 0, step);
    for (int step = 0; step < 3; ++step)
        k_gemm_cheb<<<g2, blk, SMEM_DYN3>>>(Lc, 1, step);

    // W_j = X @ Tc_j (2-term)
    k_gemm_w<<<dim3(12, 12, 4), blk, SMEM_DYN2>>>();
    // W^T hi for the Z-stage B operands
    k_trW<<<dim3(NM / 32, NM / 32, 4), blkT>>>();
    // Y_i = Tr_i @ X (1-term)
    k_gemm_y<<<dim3(12, 12, 4), blk, SMEM_DYN1>>>();
    // Z_ij = Tr_i @ W_j (1-term)
    k_gemm_z<<<dim3(12, 12, 16), blk, SMEM_DYN1>>>();

    // final 25-term mix
    k_mix<<<N2 / 512, 256>>>(x, theta, bias, out);
}

// round 12
// speedup vs baseline: 4.5446x; 1.1945x over previous
#include <cuda_runtime.h>
#include <cuda_fp16.h>
#include <cstdint>

// ============================================================================
// BilinearChebConv via mma.sync (fp16 split GEMMs, fp32 accumulate)
// out[o] = sum_{i,j} theta[i,j,o] * (Tr_i @ X @ Tc_j) + bias[o]
// M = N = 1536, orders 4/4, OUT = 32.
// R12: MMA units 46 -> 36.
//   - Chebyshev chain -> 2-term, restructured: T2 = 2L@L - I,
//     T3 = 2T2@L - L, T4 = 2T2@T2 - I (shorter error chains; steps 1&2
//     depend only on T2 -> batched in one launch).
//   - W -> 1-term (Xh @ Tch).
//   - Y, Z stay 1-term (unchanged; control group).
// Error model: ~1.3e-4 per fp16-rounded operand, quadrature -> ~4-5e-4 total.
// ============================================================================

constexpr int NM   = 1536;
constexpr int N2   = NM * NM;
constexpr int OUTC = 32;

constexpr int BK     = 64;                  // k per stage (64 fp16 = 128B row)
constexpr int NKT    = NM / BK;             // 24
constexpr int PLANE  = 128 * 128;           // bytes per operand plane per stage
constexpr int STAGE2 = 3 * PLANE;           // Ah|Al|Bh = 48 KB (2-term)
constexpr int STAGE1 = 2 * PLANE;           // Ah|Bh    = 32 KB (1-term)
constexpr unsigned SMEM_DYN2 = 3 * STAGE2;  // 144 KB
constexpr unsigned SMEM_DYN1 = 3 * STAGE1;  //  96 KB

// ----------------------------------------------------------------------------
// Scratch (no cudaMalloc allowed -> __device__ globals)
__device__ float g_Tr32[3][N2];
__device__ float g_Tc32[3][N2];
__device__ float g_W32[4][N2];          // W_j = X @ Tc_j      (= Z_{0,j})
__device__ float g_Y32[4][N2];          // Y_i = Tr_i @ X      (= Z_{i,0})
__device__ float g_Z32[16][N2];         // Z_ij = Tr_i @ W_j,  i,j = 1..4
// fp16 hi/lo operand planes (all B operands stored as N x K)
__device__ __half g_Xh[N2],  g_Xl[N2];      // X (row-major; Xl now unused)
__device__ __half g_XTh[N2];                // X^T hi (B for Y-stage)
__device__ __half g_Lrh[N2], g_Lrl[N2];
__device__ __half g_Lch[N2], g_Lcl[N2];
__device__ __half g_Trh[3][N2], g_Trl[3][N2];   // lo used only for T2 (A op)
__device__ __half g_Tch[3][N2], g_Tcl[3][N2];
__device__ __half g_WTh[4][N2];                 // W_j^T hi (B for Z)

// ----------------------------------------------------------------------------
// PTX helpers (all baseline sm_80+ instructions)
// ----------------------------------------------------------------------------
__device__ __forceinline__ uint32_t smem_u32(const void* p) {
    uint32_t a;
    asm("{ .reg .u64 t; cvta.to.shared.u64 t, %1; cvt.u32.u64 %0, t; }"
        : "=r"(a) : "l"(p));
    return a;
}
__device__ __forceinline__ void cpa16(uint32_t s, const void* g) {
    asm volatile("cp.async.cg.shared.global [%0], [%1], 16;\n" :: "r"(s), "l"(g));
}
__device__ __forceinline__ void cp_commit() {
    asm volatile("cp.async.commit_group;\n" ::: "memory");
}
__device__ __forceinline__ void cp_wait2() {
    asm volatile("cp.async.wait_group 2;\n" ::: "memory");
}
__device__ __forceinline__ void ldsm4(uint32_t* r, uint32_t a) {
    asm volatile("ldmatrix.sync.aligned.m8n8.x4.shared.b16 {%0,%1,%2,%3}, [%4];"
                 : "=r"(r[0]), "=r"(r[1]), "=r"(r[2]), "=r"(r[3]) : "r"(a));
}
__device__ __forceinline__ void mma16816(float* c, const uint32_t* a,
                                         uint32_t b0, uint32_t b1) {
    asm volatile("mma.sync.aligned.m16n8k16.row.col.f32.f16.f16.f32 "
                 "{%0,%1,%2,%3}, {%4,%5,%6,%7}, {%8,%9}, {%0,%1,%2,%3};"
                 : "+f"(c[0]), "+f"(c[1]), "+f"(c[2]), "+f"(c[3])
                 : "r"(a[0]), "r"(a[1]), "r"(a[2]), "r"(a[3]), "r"(b0), "r"(b1));
}

extern __shared__ char dsm[];

// ----------------------------------------------------------------------------
// 2-term core GEMM: C(128x128) += (Ah + Al) * Bh over K=1536.
// Block = 512 threads, 16 warps of 32x32. acc[2][4][4] per thread.
// ----------------------------------------------------------------------------
__device__ __forceinline__ void gemm_main2(
    const __half* __restrict__ Ah, const __half* __restrict__ Al,
    const __half* __restrict__ Bh,
    float (&acc)[2][4][4])
{
    const uint32_t sbase = smem_u32(dsm);
    const int tid = threadIdx.x, lane = tid & 31, wid = tid >> 5;
    const int wm = (wid & 3) * 32, wn = (wid >> 2) * 32;
    const int l15 = lane & 15, lhi = lane >> 4;
    const int bm = blockIdx.y * 128, bn = blockIdx.x * 128;
    const int lc = tid & 7, lr = tid >> 3;

    auto load_stage = [&](int st, int kc) {
        const uint32_t sb = sbase + st * STAGE2;
#pragma unroll
        for (int rr = 0; rr < 128; rr += 64) {
            const int r = lr + rr;
            const uint32_t off = (uint32_t)(r * 128) + (uint32_t)((lc ^ (r & 7)) << 4);
            const size_t ga = (size_t)(bm + r) * NM + kc + lc * 8;
            const size_t gb = (size_t)(bn + r) * NM + kc + lc * 8;
            cpa16(sb + 0 * PLANE + off, Ah + ga);
            cpa16(sb + 1 * PLANE + off, Al + ga);
            cpa16(sb + 2 * PLANE + off, Bh + gb);
        }
    };

    load_stage(0, 0);      cp_commit();
    load_stage(1, BK);     cp_commit();
    load_stage(2, 2 * BK); cp_commit();

    for (int kt = 0; kt < NKT; ++kt) {
        cp_wait2();
        __syncthreads();
        const uint32_t sb = sbase + (kt % 3) * STAGE2;
#pragma unroll
        for (int kh = 0; kh < 4; ++kh) {
            uint32_t ahf[2][4], alf[2][4];
            const int chunkL = (kh << 1) | lhi;
#pragma unroll
            for (int mt = 0; mt < 2; ++mt) {
                const int r = wm + mt * 16 + l15;
                const uint32_t off = (uint32_t)(r * 128) +
                                     (uint32_t)((chunkL ^ (r & 7)) << 4);
                ldsm4(ahf[mt], sb + 0 * PLANE + off);
                ldsm4(alf[mt], sb + 1 * PLANE + off);
            }
#pragma unroll
            for (int g = 0; g < 2; ++g) {
                uint32_t bh4[4];
                const int r = wn + g * 16 + l15;
                const uint32_t off = (uint32_t)(r * 128) +
                                     (uint32_t)((chunkL ^ (r & 7)) << 4);
                ldsm4(bh4, sb + 2 * PLANE + off);
#pragma unroll
                for (int mt = 0; mt < 2; ++mt)
#pragma unroll
                    for (int j = 0; j < 2; ++j)
                        mma16816(acc[mt][g * 2 + j], ahf[mt], bh4[j], bh4[j + 2]);
#pragma unroll
                for (int mt = 0; mt < 2; ++mt)
#pragma unroll
                    for (int j = 0; j < 2; ++j)
                        mma16816(acc[mt][g * 2 + j], alf[mt], bh4[j], bh4[j + 2]);
            }
        }
        __syncthreads();
        if (kt + 3 < NKT) load_stage(kt % 3, (kt + 3) * BK);
        cp_commit();
    }
}

// ----------------------------------------------------------------------------
// 1-term core GEMM: C(128x128) += Ah * Bh over K=1536. Two smem planes.
// ----------------------------------------------------------------------------
__device__ __forceinline__ void gemm_main1(
    const __half* __restrict__ Ah, const __half* __restrict__ Bh,
    float (&acc)[2][4][4])
{
    const uint32_t sbase = smem_u32(dsm);
    const int tid = threadIdx.x, lane = tid & 31, wid = tid >> 5;
    const int wm = (wid & 3) * 32, wn = (wid >> 2) * 32;
    const int l15 = lane & 15, lhi = lane >> 4;
    const int bm = blockIdx.y * 128, bn = blockIdx.x * 128;
    const int lc = tid & 7, lr = tid >> 3;

    auto load_stage = [&](int st, int kc) {
        const uint32_t sb = sbase + st * STAGE1;
#pragma unroll
        for (int rr = 0; rr < 128; rr += 64) {
            const int r = lr + rr;
            const uint32_t off = (uint32_t)(r * 128) + (uint32_t)((lc ^ (r & 7)) << 4);
            const size_t ga = (size_t)(bm + r) * NM + kc + lc * 8;
            const size_t gb = (size_t)(bn + r) * NM + kc + lc * 8;
            cpa16(sb + 0 * PLANE + off, Ah + ga);
            cpa16(sb + 1 * PLANE + off, Bh + gb);
        }
    };

    load_stage(0, 0);      cp_commit();
    load_stage(1, BK);     cp_commit();
    load_stage(2, 2 * BK); cp_commit();

    for (int kt = 0; kt < NKT; ++kt) {
        cp_wait2();
        __syncthreads();
        const uint32_t sb = sbase + (kt % 3) * STAGE1;
#pragma unroll
        for (int kh = 0; kh < 4; ++kh) {
            uint32_t ahf[2][4];
            const int chunkL = (kh << 1) | lhi;
#pragma unroll
            for (int mt = 0; mt < 2; ++mt) {
                const int r = wm + mt * 16 + l15;
                const uint32_t off = (uint32_t)(r * 128) +
                                     (uint32_t)((chunkL ^ (r & 7)) << 4);
                ldsm4(ahf[mt], sb + 0 * PLANE + off);
            }
#pragma unroll
            for (int g = 0; g < 2; ++g) {
                uint32_t bh4[4];
                const int r = wn + g * 16 + l15;
                const uint32_t off = (uint32_t)(r * 128) +
                                     (uint32_t)((chunkL ^ (r & 7)) << 4);
                ldsm4(bh4, sb + 1 * PLANE + off);
#pragma unroll
                for (int mt = 0; mt < 2; ++mt)
#pragma unroll
                    for (int j = 0; j < 2; ++j)
                        mma16816(acc[mt][g * 2 + j], ahf[mt], bh4[j], bh4[j + 2]);
            }
        }
        __syncthreads();
        if (kt + 3 < NKT) load_stage(kt % 3, (kt + 3) * BK);
        cp_commit();
    }
}

// plain fp32 epilogue -------------------------------------------------------
__device__ __forceinline__ void epi_plain(float (&acc)[2][4][4], float* __restrict__ C)
{
    const int tid = threadIdx.x, lane = tid & 31, wid = tid >> 5;
    const int wm = (wid & 3) * 32, wn = (wid >> 2) * 32;
    const int bm = blockIdx.y * 128, bn = blockIdx.x * 128;
    const int l4 = lane >> 2, l2 = (lane & 3) * 2;
#pragma unroll
    for (int mt = 0; mt < 2; ++mt)
#pragma unroll
        for (int h = 0; h < 2; ++h) {
            const int row = bm + wm + mt * 16 + l4 + h * 8;
#pragma unroll
            for (int nt = 0; nt < 4; ++nt) {
                const int col = bn + wn + nt * 8 + l2;
                *(float2*)(C + (size_t)row * NM + col) =
                    make_float2(acc[mt][nt][2 * h], acc[mt][nt][2 * h + 1]);
            }
        }
}

// Chebyshev epilogue: C = 2*acc - D (D = I when null); writes fp32 + hi
// (+ lo when writeLo, for planes reused as A operands).
__device__ __forceinline__ void epi_cheb(float (&acc)[2][4][4],
                                         const float* __restrict__ D,
                                         float* __restrict__ C,
                                         __half* __restrict__ Ho,
                                         __half* __restrict__ Lo,
                                         bool writeLo)
{
    const int tid = threadIdx.x, lane = tid & 31, wid = tid >> 5;
    const int wm = (wid & 3) * 32, wn = (wid >> 2) * 32;
    const int bm = blockIdx.y * 128, bn = blockIdx.x * 128;
    const int l4 = lane >> 2, l2 = (lane & 3) * 2;
#pragma unroll
    for (int mt = 0; mt < 2; ++mt)
#pragma unroll
        for (int h = 0; h < 2; ++h) {
            const int row = bm + wm + mt * 16 + l4 + h * 8;
#pragma unroll
            for (int nt = 0; nt < 4; ++nt) {
                const int col = bn + wn + nt * 8 + l2;
                const size_t off = (size_t)row * NM + col;
                float2 d;
                if (D) d = *(const float2*)(D + off);
                else   d = make_float2(row == col ? 1.f : 0.f,
                                       row == col + 1 ? 1.f : 0.f);
                const float vx = 2.f * acc[mt][nt][2 * h]     - d.x;
                const float vy = 2.f * acc[mt][nt][2 * h + 1] - d.y;
                *(float2*)(C + off) = make_float2(vx, vy);
                const __half hx = __float2half_rn(vx);
                const __half hy = __float2half_rn(vy);
                __half2 q;
                q.x = hx; q.y = hy;
                *(__half2*)(Ho + off) = q;
                if (writeLo) {
                    q.x = __float2half_rn(vx - __half2float(hx));
                    q.y = __float2half_rn(vy - __half2float(hy));
                    *(__half2*)(Lo + off) = q;
                }
            }
        }
}

// ----------------------------------------------------------------------------
// Kernels
// ----------------------------------------------------------------------------

// Step 0 (both sides batched, z = side): T2 = 2*L@L - I  (2-term, A = L hi/lo)
__global__ void __launch_bounds__(512)
k_cheb0(const float* __restrict__ Lr, const float* __restrict__ Lc)
{
    const int side = blockIdx.z;
    const __half* Lh = side ? g_Lch : g_Lrh;
    const __half* Ll = side ? g_Lcl : g_Lrl;
    float acc[2][4][4] = {};
    gemm_main2(Lh, Ll, Lh, acc);
    epi_cheb(acc, nullptr,
             side ? g_Tc32[0] : g_Tr32[0],
             side ? g_Tch[0]  : g_Trh[0],
             side ? g_Tcl[0]  : g_Trl[0], true);
}

// Steps 1&2 batched (z = side*2 + (step-1)); both depend only on T2.
//   step1: T3 = 2*T2@L  - L   (A = T2 hi/lo, B = L hi,  D = L)
//   step2: T4 = 2*T2@T2 - I   (A = T2 hi/lo, B = T2 hi, D = I)
__global__ void __launch_bounds__(512)
k_cheb12(const float* __restrict__ Lr, const float* __restrict__ Lc)
{
    const int z = blockIdx.z;
    const int side = z >> 1, step = 1 + (z & 1);
    const __half* T2h = side ? g_Tch[0] : g_Trh[0];
    const __half* T2l = side ? g_Tcl[0] : g_Trl[0];
    const __half* Lh  = side ? g_Lch : g_Lrh;
    const __half* Bh  = (step == 1) ? Lh : T2h;
    const float*  D   = (step == 1) ? (side ? Lc : Lr) : nullptr;

    float acc[2][4][4] = {};
    gemm_main2(T2h, T2l, Bh, acc);
    epi_cheb(acc, D,
             side ? g_Tc32[step] : g_Tr32[step],
             side ? g_Tch[step]  : g_Trh[step],
             side ? g_Tcl[step]  : g_Trl[step], false);
}

// W_j = X @ Tc_j (1-term): j-1 = blockIdx.z
__global__ void __launch_bounds__(512)
k_gemm_w()
{
    const int z = blockIdx.z;
    const __half* Bh = (z == 0) ? g_Lch : g_Tch[z - 1];
    float acc[2][4][4] = {};
    gemm_main1(g_Xh, Bh, acc);
    epi_plain(acc, g_W32[z]);
}

// Y_i = Tr_i @ X (1-term): i-1 = blockIdx.z; B = X^T hi.
__global__ void __launch_bounds__(512)
k_gemm_y()
{
    const int z = blockIdx.z;
    const __half* Ah = (z == 0) ? g_Lrh : g_Trh[z - 1];
    float acc[2][4][4] = {};
    gemm_main1(Ah, g_XTh, acc);
    epi_plain(acc, g_Y32[z]);
}

// Z_ij = Tr_i @ W_j (1-term): z = (i-1)*4 + (j-1).
__global__ void __launch_bounds__(512)
k_gemm_z()
{
    const int z = blockIdx.z;
    const int i = z >> 2, j = z & 3;
    const __half* Ah = (i == 0) ? g_Lrh : g_Trh[i - 1];
    float acc[2][4][4] = {};
    gemm_main1(Ah, g_WTh[j], acc);
    epi_plain(acc, g_Z32[z]);
}

// ----------------------------------------------------------------------------
// fp32 -> fp16 hi/lo conversion of inputs (z: 0=X, 1=Lr, 2=Lc)
__global__ void __launch_bounds__(256)
k_cvt(const float* __restrict__ x, const float* __restrict__ Lr,
      const float* __restrict__ Lc)
{
    const int zz = blockIdx.z;
    const float* s = (zz == 0) ? x : (zz == 1) ? Lr : Lc;
    __half* H = (zz == 0) ? g_Xh : (zz == 1) ? g_Lrh : g_Lch;
    __half* L = (zz == 0) ? g_Xl : (zz == 1) ? g_Lrl : g_Lcl;
    const int i = (blockIdx.x * 256 + threadIdx.x) * 4;
    float4 v = *(const float4*)(s + i);
    __half h0 = __float2half_rn(v.x), h1 = __float2half_rn(v.y);
    __half h2 = __float2half_rn(v.z), h3 = __float2half_rn(v.w);
    __half2 p;
    p.x = h0; p.y = h1; *(__half2*)(H + i)     = p;
    p.x = h2; p.y = h3; *(__half2*)(H + i + 2) = p;
    p.x = __float2half_rn(v.x - __half2float(h0));
    p.y = __float2half_rn(v.y - __half2float(h1));
    *(__half2*)(L + i) = p;
    p.x = __float2half_rn(v.z - __half2float(h2));
    p.y = __float2half_rn(v.w - __half2float(h3));
    *(__half2*)(L + i + 2) = p;
}

// X^T hi
__global__ void __launch_bounds__(256)
k_cvtT(const float* __restrict__ X)
{
    __shared__ float t[32][33];
    const int tx = threadIdx.x, ty = threadIdx.y;
    const int n0 = blockIdx.x * 32, m0 = blockIdx.y * 32;
#pragma unroll
    for (int i = 0; i < 4; ++i)
        t[ty + 8 * i][tx] = X[(size_t)(m0 + ty + 8 * i) * NM + n0 + tx];
    __syncthreads();
#pragma unroll
    for (int i = 0; i < 4; ++i) {
        const int nl = ty + 8 * i;
        g_XTh[(size_t)(n0 + nl) * NM + m0 + tx] = __float2half_rn(t[tx][nl]);
    }
}

// W^T hi (z = j-1)
__global__ void __launch_bounds__(256)
k_trW()
{
    const int z = blockIdx.z;
    const float* S = g_W32[z];
    __half* TH = g_WTh[z];
    __shared__ float t[32][33];
    const int tx = threadIdx.x, ty = threadIdx.y;
    const int n0 = blockIdx.x * 32, m0 = blockIdx.y * 32;
#pragma unroll
    for (int i = 0; i < 4; ++i)
        t[ty + 8 * i][tx] = S[(size_t)(m0 + ty + 8 * i) * NM + n0 + tx];
    __syncthreads();
#pragma unroll
    for (int i = 0; i < 4; ++i) {
        const int nl = ty + 8 * i;
        TH[(size_t)(n0 + nl) * NM + m0 + tx] = __float2half_rn(t[tx][nl]);
    }
}

// ----------------------------------------------------------------------------
// Final mix: out[o,m,n] = bias[o] + sum_t theta[t,o] * plane_t[m,n]
__global__ void __launch_bounds__(256)
k_mix(const float* __restrict__ x, const float* __restrict__ theta,
      const float* __restrict__ bias, float* __restrict__ out)
{
    __shared__ float sh_th[25 * OUTC];
    __shared__ float sh_b[OUTC];
    const int tid = threadIdx.x;
    for (int t = tid; t < 25 * OUTC; t += 256) sh_th[t] = theta[t];
    if (tid < OUTC) sh_b[tid] = bias[tid];
    __syncthreads();

    const int off = (blockIdx.x * 256 + tid) * 2;

    float2 v[25];
    v[0] = *(const float2*)(x + off);
#pragma unroll
    for (int j = 1; j <= 4; ++j) v[j] = *(const float2*)(g_W32[j - 1] + off);
#pragma unroll
    for (int i = 1; i <= 4; ++i) v[i * 5] = *(const float2*)(g_Y32[i - 1] + off);
#pragma unroll
    for (int i = 1; i <= 4; ++i)
#pragma unroll
        for (int j = 1; j <= 4; ++j)
            v[i * 5 + j] = *(const float2*)(g_Z32[(i - 1) * 4 + (j - 1)] + off);

#pragma unroll
    for (int o = 0; o < OUTC; ++o) {
        float sx = sh_b[o], sy = sh_b[o];
#pragma unroll
        for (int t = 0; t < 25; ++t) {
            const float w = sh_th[t * OUTC + o];
            sx += w * v[t].x;
            sy += w * v[t].y;
        }
        *(float2*)(out + (size_t)o * N2 + off) = make_float2(sx, sy);
    }
}

// ----------------------------------------------------------------------------
extern "C" void kernel_launch(void* const* d_in, const int* in_sizes, int n_in,
                              void* d_out, int out_size)
{
    const float* x     = (const float*)d_in[0];
    const float* Lr    = (const float*)d_in[1];
    const float* Lc    = (const float*)d_in[2];
    const float* theta = (const float*)d_in[3];
    const float* bias  = (const float*)d_in[4];
    float* out = (float*)d_out;

    cudaFuncSetAttribute(k_cheb0,  cudaFuncAttributeMaxDynamicSharedMemorySize, SMEM_DYN2);
    cudaFuncSetAttribute(k_cheb12, cudaFuncAttributeMaxDynamicSharedMemorySize, SMEM_DYN2);
    cudaFuncSetAttribute(k_gemm_w, cudaFuncAttributeMaxDynamicSharedMemorySize, SMEM_DYN1);
    cudaFuncSetAttribute(k_gemm_y, cudaFuncAttributeMaxDynamicSharedMemorySize, SMEM_DYN1);
    cudaFuncSetAttribute(k_gemm_z, cudaFuncAttributeMaxDynamicSharedMemorySize, SMEM_DYN1);

    const dim3 blk(512);
    const dim3 blkT(32, 8);
    const dim3 gT(NM / 32, NM / 32, 1);

    // input conversions
    k_cvt<<<dim3(N2 / 1024, 1, 3), 256>>>(x, Lr, Lc);
    k_cvtT<<<gT, blkT>>>(x);

    // Chebyshev: T2 both sides, then {T3, T4} x both sides (depend on T2 only)
    k_cheb0 <<<dim3(12, 12, 2), blk, SMEM_DYN2>>>(Lr, Lc);
    k_cheb12<<<dim3(12, 12, 4), blk, SMEM_DYN2>>>(Lr, Lc);

    // W_j = X @ Tc_j (1-term)
    k_gemm_w<<<dim3(12, 12, 4), blk, SMEM_DYN1>>>();
    // W^T hi for the Z-stage B operands
    k_trW<<<dim3(NM / 32, NM / 32, 4), blkT>>>();
    // Y_i = Tr_i @ X (1-term)
    k_gemm_y<<<dim3(12, 12, 4), blk, SMEM_DYN1>>>();
    // Z_ij = Tr_i @ W_j (1-term)
    k_gemm_z<<<dim3(12, 12, 16), blk, SMEM_DYN1>>>();

    // final 25-term mix
    k_mix<<<N2 / 512, 256>>>(x, theta, bias, out);
}